// round 10
// baseline (speedup 1.0000x reference)
#include <cuda_runtime.h>
#include <cuda_bf16.h>
#include <cuda_fp16.h>
#include <cstdint>

#define DEV_INLINE __device__ __forceinline__

constexpr int L_   = 100;
constexpr int B_   = 32;
constexpr int E_   = 512;
constexpr int F_   = 256;
constexpr int M_   = 128;
constexpr int D_   = 258;
constexpr int NPAIR = L_ * L_;                 // 10000
constexpr int NTILE = (NPAIR + 127) / 128;     // 79

// ---------------- scratch (device globals; no allocation allowed) ----------------
__device__ float g_act1[B_ * F_ * L_];
__device__ float g_act2[B_ * F_ * L_];
__device__ float g_csum [4][F_][B_];           // per-layer, per-channel, per-batch sums
__device__ float g_csum2[4][F_][B_];
__device__ float g_A[B_ * L_ * M_];
__device__ float g_C[B_ * L_ * M_];
__device__ float g_part[B_ * NTILE * M_];
// fragment-packed fp16 weights: [layer][n*32 + slot] = {wh0, wh1, wl0, wl1}
__device__ __align__(16) uint4 g_wpack2[3][128 * 32];

DEV_INLINE float lrelu(float z) { return fmaxf(z, 0.f) + 0.1f * fminf(z, 0.f); }

DEV_INLINE uint32_t pack_h2(float x0, float x1) {
    __half2 h = __floats2half2_rn(x0, x1);
    return *reinterpret_cast<uint32_t*>(&h);
}

DEV_INLINE void mma16816_f16(float c[4], const uint32_t a[4], uint32_t b0, uint32_t b1) {
    asm volatile(
        "mma.sync.aligned.m16n8k16.row.col.f32.f16.f16.f32 "
        "{%0,%1,%2,%3}, {%4,%5,%6,%7}, {%8,%9}, {%0,%1,%2,%3};"
        : "+f"(c[0]), "+f"(c[1]), "+f"(c[2]), "+f"(c[3])
        : "r"(a[0]), "r"(a[1]), "r"(a[2]), "r"(a[3]), "r"(b0), "r"(b1));
}

// =================================================================================
// Conv1d (K=3, pad 1) + bias + leakyReLU, with FUSED BN:
//  - consumer side: reduces previous layer's per-(f,b) partial sums into a smem
//    affine table at block start (deterministic fixed-order sum)
//  - producer side: writes this layer's per-(f,b) partial sums for the next stage
// =================================================================================
constexpr int EC = 32;
constexpr int FT = 16;

template <int EIN, bool FIRST>
__global__ void __launch_bounds__(128) conv_kernel(
    const float* __restrict__ in_ext, int src,
    int prev_layer, const float* __restrict__ ga_prev, const float* __restrict__ be_prev,
    const float* __restrict__ w, const float* __restrict__ cb,
    int dst, int stat_layer)
{
    __shared__ float in_s[EC][L_ + 2];
    __shared__ float w_s[EC][3][FT];
    __shared__ float aff_a_s[F_], aff_b_s[F_];

    const int b  = blockIdx.x;
    const int f0 = blockIdx.y * FT;
    const int t  = threadIdx.x;

    const float* in  = FIRST ? in_ext : (src ? g_act2 : g_act1);
    float*       out = dst ? g_act2 : g_act1;

    if (!FIRST) {
        // build input-affine from previous layer's partial stats
        for (int ch = t; ch < F_; ch += 128) {
            float s = 0.f, s2 = 0.f;
#pragma unroll
            for (int bb = 0; bb < B_; bb++) {
                s  += g_csum [prev_layer][ch][bb];
                s2 += g_csum2[prev_layer][ch][bb];
            }
            const float inv_n = 1.f / (float)(B_ * L_);
            float mean = s * inv_n;
            float var  = s2 * inv_n - mean * mean;
            float a = ga_prev[ch] * rsqrtf(var + 1e-5f);
            aff_a_s[ch] = a;
            aff_b_s[ch] = be_prev[ch] - mean * a;
        }
        __syncthreads();
    }

    float acc[FT];
#pragma unroll
    for (int i = 0; i < FT; i++) acc[i] = 0.f;

    for (int e0 = 0; e0 < EIN; e0 += EC) {
        __syncthreads();
        for (int c = t; c < EC * (L_ + 2); c += 128) {
            int e, lo;
            if (FIRST) { e = c & (EC - 1); lo = c >> 5; }
            else       { e = c / (L_ + 2); lo = c - e * (L_ + 2); }
            int l = lo - 1;
            float v = 0.f;
            if (l >= 0 && l < L_) {
                if (FIRST) {
                    v = in[(size_t)l * (B_ * E_) + (size_t)b * E_ + (e0 + e)];
                } else {
                    v = in[((size_t)b * EIN + (e0 + e)) * L_ + l];
                    v = aff_a_s[e0 + e] * v + aff_b_s[e0 + e];
                }
            }
            in_s[e][lo] = v;
        }
        for (int c = t; c < EC * 3 * FT; c += 128) {
            int fl = c & (FT - 1);
            int rest = c >> 4;
            int k = rest % 3;
            int e = rest / 3;
            w_s[e][k][fl] = w[((size_t)(f0 + fl) * EIN + (e0 + e)) * 3 + k];
        }
        __syncthreads();

        if (t < L_) {
#pragma unroll 4
            for (int e = 0; e < EC; e++) {
                float x0 = in_s[e][t];
                float x1 = in_s[e][t + 1];
                float x2 = in_s[e][t + 2];
#pragma unroll
                for (int fl = 0; fl < FT; fl++) {
                    acc[fl] += x0 * w_s[e][0][fl];
                    acc[fl] += x1 * w_s[e][1][fl];
                    acc[fl] += x2 * w_s[e][2][fl];
                }
            }
        }
    }

    // epilogue: write outputs + per-(f,b) partial sums for this layer's BN
    __syncthreads();                       // in_s reads done; reuse as z buffer
    float* zb = &in_s[0][0];               // [FT][L_] = 1600 floats <= 3264
    if (t < L_) {
#pragma unroll
        for (int fl = 0; fl < FT; fl++) {
            float z = lrelu(acc[fl] + cb[f0 + fl]);
            out[((size_t)b * F_ + (f0 + fl)) * L_ + t] = z;
            zb[fl * L_ + t] = z;
        }
    }
    __syncthreads();
    {
        int ch = t >> 3;                   // 16 channels x 8 threads
        int j  = t & 7;
        float s = 0.f, s2 = 0.f;
        for (int i = j; i < L_; i += 8) {
            float v = zb[ch * L_ + i];
            s += v; s2 += v * v;
        }
#pragma unroll
        for (int o = 4; o > 0; o >>= 1) {
            s  += __shfl_down_sync(0xffffffffu, s,  o, 8);
            s2 += __shfl_down_sync(0xffffffffu, s2, o, 8);
        }
        if (j == 0) {
            g_csum [stat_layer][f0 + ch][b] = s;
            g_csum2[stat_layer][f0 + ch][b] = s2;
        }
    }
}

// =================================================================================
// A / C projections with fused hb, fused layer-4 affine, and weight packing
// folded in as blockIdx.y == 5.
// =================================================================================
constexpr int LT = 20;

__global__ void __launch_bounds__(256) ac_kernel(
    const float* __restrict__ W1, const float* __restrict__ b1,
    const float* __restrict__ h,
    const float* __restrict__ ga4, const float* __restrict__ be4,
    const float* __restrict__ W2, const float* __restrict__ W3,
    const float* __restrict__ W4)
{
    if (blockIdx.y == 5) {
        // ---- pack W2/W3/W4 into fp16 hi/lo fragment uint4s ----
        for (int idx = blockIdx.x * 256 + threadIdx.x; idx < 3 * 128 * 32;
             idx += 32 * 256) {
            int layer = idx >> 12;
            int rem   = idx & 4095;
            int n = rem >> 5;
            int s = rem & 31;
            int c = s >> 2;
            int t = s & 3;
            const float* W = layer == 0 ? W2 : (layer == 1 ? W3 : W4);
            uint32_t hw[2], lw[2];
#pragma unroll
            for (int j = 0; j < 2; j++) {
                int kw = 8 * c + 4 * j + t;
                float w0 = W[(size_t)(2 * kw) * 128 + n];
                float w1 = W[(size_t)(2 * kw + 1) * 128 + n];
                __half h0 = __float2half_rn(w0);
                __half h1 = __float2half_rn(w1);
                float r0 = w0 - __half2float(h0);
                float r1 = w1 - __half2float(h1);
                hw[j] = pack_h2(__half2float(h0), __half2float(h1));
                lw[j] = pack_h2(r0, r1);
            }
            int slot = (c * 4 + t) ^ ((n & 1) * 4);
            g_wpack2[layer][n * 32 + slot] = make_uint4(hw[0], hw[1], lw[0], lw[1]);
        }
        return;
    }

    __shared__ float xf[LT][D_];
    __shared__ float aff_a_s[F_], aff_b_s[F_];
    __shared__ float hb_s[M_];

    const int b  = blockIdx.x;
    const int l0 = blockIdx.y * LT;
    const int t  = threadIdx.x;

    // ---- layer-4 affine from partial stats ----
    if (t < F_) {
        int ch = t;
        float s = 0.f, s2 = 0.f;
#pragma unroll
        for (int bb = 0; bb < B_; bb++) {
            s  += g_csum [3][ch][bb];
            s2 += g_csum2[3][ch][bb];
        }
        const float inv_n = 1.f / (float)(B_ * L_);
        float mean = s * inv_n;
        float var  = s2 * inv_n - mean * mean;
        float a = ga4[ch] * rsqrtf(var + 1e-5f);
        aff_a_s[ch] = a;
        aff_b_s[ch] = be4[ch] - mean * a;
    }
    __syncthreads();

    // ---- build xf ----
    for (int c = t; c < LT * D_; c += 256) {
        int ch = c / LT;
        int ll = c - ch * LT;
        int l  = l0 + ll;
        float v;
        if (ch < F_) {
            v = aff_a_s[ch] * g_act2[((size_t)b * F_ + ch) * L_ + l] + aff_b_s[ch];
        } else if (ch == F_) {
            v = ((float)l / 10.0f - 2.0f) * 0.5f;
        } else {
            v = ((float)(l % 10) - 2.0f) * 0.5f;
        }
        xf[ll][ch] = v;
    }

    // ---- fused hb: hb_s[n] = h[b] @ Wc[:,n] + b1[n] ----
    if (t < 128) {
        const float* Wc = W1 + (size_t)(2 * D_) * M_;
        const float* hb_row = h + (size_t)b * E_;
        float acc = b1[t];
#pragma unroll 4
        for (int k = 0; k < E_; k++) acc += hb_row[k] * Wc[(size_t)k * M_ + t];
        hb_s[t] = acc;
    }
    __syncthreads();

    const int n  = t & 127;
    const int lg = t >> 7;

    float accA[LT / 2], accC[LT / 2];
#pragma unroll
    for (int i = 0; i < LT / 2; i++) { accA[i] = 0.f; accC[i] = 0.f; }

    const float* Wa = W1;
    const float* Wb = W1 + (size_t)D_ * M_;
#pragma unroll 2
    for (int c = 0; c < D_; c++) {
        float wa = Wa[(size_t)c * M_ + n];
        float wb = Wb[(size_t)c * M_ + n];
#pragma unroll
        for (int i = 0; i < LT / 2; i++) {
            float x = xf[2 * i + lg][c];
            accA[i] += x * wa;
            accC[i] += x * wb;
        }
    }
    float hbv = hb_s[n];
#pragma unroll
    for (int i = 0; i < LT / 2; i++) {
        int l = l0 + 2 * i + lg;
        g_A[((size_t)b * L_ + l) * M_ + n] = accA[i];
        g_C[((size_t)b * L_ + l) * M_ + n] = accC[i] + hbv;
    }
}

// =================================================================================
// Tensor-core pairwise relation kernel — fp16 2-term split (R9, proven).
// =================================================================================
constexpr int SMEM_PW = 128 * 32 * 16;   // 65,536 B

DEV_INLINE void stageW(uint4* smW, int layer, int tid) {
    const uint4* src = g_wpack2[layer];
#pragma unroll
    for (int it = 0; it < 16; it++)
        smW[it * 256 + tid] = src[it * 256 + tid];
}

__global__ void __launch_bounds__(256) pairwise_mma(
    const float* __restrict__ b2, const float* __restrict__ b3,
    const float* __restrict__ b4)
{
    extern __shared__ char smraw[];
    uint4* smW    = (uint4*)smraw;
    float* s_part = (float*)smraw;      // reused after final sync

    const int tile = blockIdx.x;
    const int b    = blockIdx.y;
    const int row0 = tile * 128;
    const int tid  = threadIdx.x;
    const int w    = tid >> 5;
    const int lane = tid & 31;
    const int g    = lane >> 2;
    const int t    = lane & 3;

    // ---- build layer-1 A fragments from global: g1 = lrelu(C_i + A_j), fp16 ----
    uint32_t Ah[8][4];
    const int r0 = row0 + 16 * w + g;
    const int r1 = r0 + 8;
    {
        int rc0 = r0 < NPAIR ? r0 : 0;
        int rc1 = r1 < NPAIR ? r1 : 0;
        int i0 = rc0 / 100, j0 = rc0 - (rc0 / 100) * 100;
        int i1 = rc1 / 100, j1 = rc1 - (rc1 / 100) * 100;
        const float2* C0 = (const float2*)(g_C + ((size_t)b * L_ + i0) * M_);
        const float2* A0 = (const float2*)(g_A + ((size_t)b * L_ + j0) * M_);
        const float2* C1 = (const float2*)(g_C + ((size_t)b * L_ + i1) * M_);
        const float2* A1 = (const float2*)(g_A + ((size_t)b * L_ + j1) * M_);
#pragma unroll
        for (int c = 0; c < 8; c++) {
            int idx = 8 * c + t;
            float2 cc, aa;
            cc = C0[idx];     aa = A0[idx];
            Ah[c][0] = pack_h2(lrelu(cc.x + aa.x), lrelu(cc.y + aa.y));
            cc = C1[idx];     aa = A1[idx];
            Ah[c][1] = pack_h2(lrelu(cc.x + aa.x), lrelu(cc.y + aa.y));
            cc = C0[idx + 4]; aa = A0[idx + 4];
            Ah[c][2] = pack_h2(lrelu(cc.x + aa.x), lrelu(cc.y + aa.y));
            cc = C1[idx + 4]; aa = A1[idx + 4];
            Ah[c][3] = pack_h2(lrelu(cc.x + aa.x), lrelu(cc.y + aa.y));
        }
    }

    stageW(smW, 0, tid);
    __syncthreads();

#pragma unroll
    for (int layer = 0; layer < 3; layer++) {
        float acc[16][4];
#pragma unroll
        for (int nt = 0; nt < 16; nt++)
#pragma unroll
            for (int q = 0; q < 4; q++) acc[nt][q] = 0.f;

#pragma unroll
        for (int c = 0; c < 8; c++) {
            const int base_slot = c * 4 + t;
#pragma unroll
            for (int nt = 0; nt < 16; nt++) {
                const int n = nt * 8 + g;
                uint4 f4 = smW[n * 32 + (base_slot ^ ((n & 1) * 4))];
                mma16816_f16(acc[nt], Ah[c], f4.x, f4.y);   // Ah * Wh
                mma16816_f16(acc[nt], Ah[c], f4.z, f4.w);   // Ah * Wl
            }
        }

        if (layer < 2) {
            const float* bias = layer == 0 ? b2 : b3;
#pragma unroll
            for (int nt = 0; nt < 16; nt++) {
                int col = nt * 8 + 2 * t;
                float bb0 = __ldg(bias + col);
                float bb1 = __ldg(bias + col + 1);
                float z0 = lrelu(acc[nt][0] + bb0);
                float z1 = lrelu(acc[nt][1] + bb1);
                float z2 = lrelu(acc[nt][2] + bb0);
                float z3 = lrelu(acc[nt][3] + bb1);
                int c2  = nt >> 1;
                int off = (nt & 1) * 2;
                Ah[c2][off]     = pack_h2(z0, z1);
                Ah[c2][off + 1] = pack_h2(z2, z3);
            }
            __syncthreads();
            stageW(smW, layer + 1, tid);
            __syncthreads();
        } else {
            __syncthreads();
            const bool live0 = r0 < NPAIR;
            const bool live1 = r1 < NPAIR;
#pragma unroll
            for (int nt = 0; nt < 16; nt++) {
                int col = nt * 8 + 2 * t;
                float bb0 = __ldg(b4 + col);
                float bb1 = __ldg(b4 + col + 1);
                float z0 = live0 ? lrelu(acc[nt][0] + bb0) : 0.f;
                float z1 = live0 ? lrelu(acc[nt][1] + bb1) : 0.f;
                float z2 = live1 ? lrelu(acc[nt][2] + bb0) : 0.f;
                float z3 = live1 ? lrelu(acc[nt][3] + bb1) : 0.f;
                float v0 = z0 + z2;
                float v1 = z1 + z3;
#pragma unroll
                for (int o = 4; o < 32; o <<= 1) {
                    v0 += __shfl_xor_sync(0xffffffffu, v0, o);
                    v1 += __shfl_xor_sync(0xffffffffu, v1, o);
                }
                if (g == 0) {
                    s_part[w * 128 + col]     = v0;
                    s_part[w * 128 + col + 1] = v1;
                }
            }
            __syncthreads();
            if (tid < 128) {
                float ss = 0.f;
#pragma unroll
                for (int ww = 0; ww < 8; ww++) ss += s_part[ww * 128 + tid];
                g_part[((size_t)b * NTILE + tile) * M_ + tid] = ss;
            }
        }
    }
}

// =================================================================================
// Final decoder (unchanged)
// =================================================================================
__global__ void __launch_bounds__(128) final_kernel(
    const float* __restrict__ F1, const float* __restrict__ fb1,
    const float* __restrict__ F2, const float* __restrict__ fb2,
    float* __restrict__ out)
{
    const int b = blockIdx.x;
    const int t = threadIdx.x;
    __shared__ float s_s[M_], t_s[M_];

    float acc = 0.f;
    for (int i = 0; i < NTILE; i++)
        acc += g_part[((size_t)b * NTILE + i) * M_ + t];
    s_s[t] = acc;
    __syncthreads();

    float a2 = fb1[t];
#pragma unroll 4
    for (int k = 0; k < M_; k++) a2 += s_s[k] * F1[(size_t)k * M_ + t];
    t_s[t] = lrelu(a2);
    __syncthreads();

    for (int m = t; m < 512; m += 128) {
        float a3 = fb2[m];
#pragma unroll 4
        for (int k = 0; k < M_; k++) a3 += t_s[k] * F2[(size_t)k * 512 + m];
        out[(size_t)b * 512 + m] = lrelu(a3);
    }
}

// =================================================================================
// launcher — exactly 7 launches; pairwise_mma is launch #5 (ncu -s 5 -c 1 target)
// =================================================================================
extern "C" void kernel_launch(void* const* d_in, const int* in_sizes, int n_in,
                              void* d_out, int out_size)
{
    (void)in_sizes; (void)n_in; (void)out_size;

    const float* x   = (const float*)d_in[0];
    const float* h   = (const float*)d_in[1];
    const float* cw1 = (const float*)d_in[2];
    const float* cb1 = (const float*)d_in[3];
    const float* ga1 = (const float*)d_in[4];
    const float* be1 = (const float*)d_in[5];
    const float* cw2 = (const float*)d_in[6];
    const float* cb2 = (const float*)d_in[7];
    const float* ga2 = (const float*)d_in[8];
    const float* be2 = (const float*)d_in[9];
    const float* cw3 = (const float*)d_in[10];
    const float* cb3 = (const float*)d_in[11];
    const float* ga3 = (const float*)d_in[12];
    const float* be3 = (const float*)d_in[13];
    const float* cw4 = (const float*)d_in[14];
    const float* cb4 = (const float*)d_in[15];
    const float* ga4 = (const float*)d_in[16];
    const float* be4 = (const float*)d_in[17];
    const float* W1  = (const float*)d_in[18];
    const float* b1  = (const float*)d_in[19];
    const float* W2  = (const float*)d_in[20];
    const float* b2  = (const float*)d_in[21];
    const float* W3  = (const float*)d_in[22];
    const float* b3  = (const float*)d_in[23];
    const float* W4  = (const float*)d_in[24];
    const float* b4  = (const float*)d_in[25];
    const float* F1  = (const float*)d_in[26];
    const float* fb1 = (const float*)d_in[27];
    const float* F2  = (const float*)d_in[28];
    const float* fb2 = (const float*)d_in[29];
    float* out = (float*)d_out;

    dim3 cgrid(B_, F_ / FT);

    // 0..3: conv stack with fused BN stats
    conv_kernel<E_, true ><<<cgrid, 128>>>(x, 0, 0, nullptr, nullptr, cw1, cb1, 0, 0);
    conv_kernel<F_, false><<<cgrid, 128>>>(nullptr, 0, 0, ga1, be1, cw2, cb2, 1, 1);
    conv_kernel<F_, false><<<cgrid, 128>>>(nullptr, 1, 1, ga2, be2, cw3, cb3, 0, 2);
    conv_kernel<F_, false><<<cgrid, 128>>>(nullptr, 0, 2, ga3, be3, cw4, cb4, 1, 3);

    // 4: projections (fused hb + layer-4 affine + weight packing)
    ac_kernel<<<dim3(B_, 6), 256>>>(W1, b1, h, ga4, be4, W2, W3, W4);

    // 5: tensor-core pairwise chain  <-- profiled by ncu -s 5 -c 1
    cudaFuncSetAttribute(pairwise_mma,
                         cudaFuncAttributeMaxDynamicSharedMemorySize, SMEM_PW);
    pairwise_mma<<<dim3(NTILE, B_), 256, SMEM_PW>>>(b2, b3, b4);

    // 6: decoder
    final_kernel<<<B_, 128>>>(F1, fb1, F2, fb2, out);
}

// round 11
// speedup vs baseline: 1.6051x; 1.6051x over previous
#include <cuda_runtime.h>
#include <cuda_fp16.h>
#include <cstdint>

#define DEV_INLINE __device__ __forceinline__

constexpr int L_   = 100;
constexpr int B_   = 32;
constexpr int E_   = 512;
constexpr int F_   = 256;
constexpr int M_   = 128;
constexpr int D_   = 258;
constexpr int NPAIR = L_ * L_;                 // 10000
constexpr int NTILE = (NPAIR + 127) / 128;     // 79
constexpr int NROW  = B_ * L_;                 // 3200 = 25 * 128
constexpr int RTILE = 25;

// ---------------- scratch (device globals; no allocation allowed) ----------------
// activations: [row = b*100+l][channel]  (channel contiguous)
__device__ float g_act1[NROW * F_];
__device__ float g_act2[NROW * F_];
__device__ float g_csum [4][F_][32];           // per-layer, per-channel, per-rowtile sums
__device__ float g_csum2[4][F_][32];
__device__ float g_A[B_ * L_ * M_];
__device__ float g_C[B_ * L_ * M_];
__device__ float g_part[B_ * NTILE * M_];
// fragment-packed fp16 pairwise weights: [layer][n*32 + slot] = {wh0, wh1, wl0, wl1}
__device__ __align__(16) uint4 g_wpack2[3][128 * 32];

DEV_INLINE float lrelu(float z) { return fmaxf(z, 0.f) + 0.1f * fminf(z, 0.f); }

DEV_INLINE uint32_t pack_h2(float x0, float x1) {
    __half2 h = __floats2half2_rn(x0, x1);
    return *reinterpret_cast<uint32_t*>(&h);
}

// fp16 hi/lo split of two floats -> packed regs
DEV_INLINE void split2h(float x0, float x1, uint32_t& hi, uint32_t& lo) {
    __half h0 = __float2half_rn(x0);
    __half h1 = __float2half_rn(x1);
    float r0 = x0 - __half2float(h0);
    float r1 = x1 - __half2float(h1);
    __half2 hh = __halves2half2(h0, h1);
    hi = *reinterpret_cast<uint32_t*>(&hh);
    lo = pack_h2(r0, r1);
}

DEV_INLINE void mma16816_f16(float c[4], const uint32_t a[4], uint32_t b0, uint32_t b1) {
    asm volatile(
        "mma.sync.aligned.m16n8k16.row.col.f32.f16.f16.f32 "
        "{%0,%1,%2,%3}, {%4,%5,%6,%7}, {%8,%9}, {%0,%1,%2,%3};"
        : "+f"(c[0]), "+f"(c[1]), "+f"(c[2]), "+f"(c[3])
        : "r"(a[0]), "r"(a[1]), "r"(a[2]), "r"(a[3]), "r"(b0), "r"(b1));
}

// =================================================================================
// Tensor-core Conv1d (K=3, pad 1) + bias + leakyReLU + fused BN stats.
// Rows = (b,l) 3200 = 25 tiles of 128; cols = f (128 per block, grid.y=2).
// 3 shifted GEMMs (k = input channel) accumulate into fp32 acc.
// 3-term fp16 split: Ah*Wh + Ah*Wl + Al*Wh (error ~2^-22).
// Weights split+swizzled into smem fragments on the fly at staging.
// =================================================================================
constexpr int CSMEM = 65536 + 4096 + 8192;     // weights + affine + partials

template <int EIN, bool FIRST>
__global__ void __launch_bounds__(256) conv_mma(
    const float* __restrict__ x_ext,   // FIRST only (layout L,B,E)
    int src, int prev_layer,
    const float* __restrict__ ga_prev, const float* __restrict__ be_prev,
    const float* __restrict__ cw,      // [F][EIN][3]
    const float* __restrict__ cb,
    int dst, int stat_layer)
{
    constexpr int NKC = EIN / 128;     // k-chunks per shift
    extern __shared__ char smraw[];
    uint4*  smW     = (uint4*)smraw;                       // 4096 uint4 = 64KB
    float*  aff_a_s = (float*)(smraw + 65536);             // [EIN]
    float*  aff_b_s = aff_a_s + EIN;
    float*  s_sum   = (float*)(smraw + 65536 + 4096);      // [8][128]
    float*  s_sq    = s_sum + 1024;

    const int tile  = blockIdx.x;      // 0..24
    const int fbase = blockIdx.y * 128;
    const int row0  = tile * 128;
    const int tid   = threadIdx.x;
    const int w     = tid >> 5;
    const int lane  = tid & 31;
    const int g     = lane >> 2;
    const int t     = lane & 3;

    if (!FIRST) {
        for (int ch = tid; ch < EIN; ch += 256) {
            float s = 0.f, s2 = 0.f;
#pragma unroll
            for (int tt = 0; tt < RTILE; tt++) {
                s  += g_csum [prev_layer][ch][tt];
                s2 += g_csum2[prev_layer][ch][tt];
            }
            const float inv_n = 1.f / (float)NROW;
            float mean = s * inv_n;
            float var  = s2 * inv_n - mean * mean;
            float a = ga_prev[ch] * rsqrtf(var + 1e-5f);
            aff_a_s[ch] = a;
            aff_b_s[ch] = be_prev[ch] - mean * a;
        }
        __syncthreads();
    }

    const int r0 = row0 + 16 * w + g;
    const int r1 = r0 + 8;
    const int b0r = r0 / 100, l0r = r0 - b0r * 100;
    const int b1r = r1 / 100, l1r = r1 - b1r * 100;

    const float* act_in = src ? g_act2 : g_act1;

    float acc[16][4];
#pragma unroll
    for (int nt = 0; nt < 16; nt++)
#pragma unroll
        for (int q = 0; q < 4; q++) acc[nt][q] = 0.f;

#pragma unroll 1
    for (int s = 0; s < 3; s++) {
        const bool m0 = (unsigned)(l0r + s - 1) < 100u;
        const bool m1 = (unsigned)(l1r + s - 1) < 100u;
        const float* p0;
        const float* p1;
        if (FIRST) {
            p0 = x_ext + ((size_t)(m0 ? (l0r + s - 1) : 0) * B_ + b0r) * E_;
            p1 = x_ext + ((size_t)(m1 ? (l1r + s - 1) : 0) * B_ + b1r) * E_;
        } else {
            p0 = act_in + (size_t)(m0 ? (r0 + s - 1) : r0) * EIN;
            p1 = act_in + (size_t)(m1 ? (r1 + s - 1) : r1) * EIN;
        }

#pragma unroll 1
        for (int kc = 0; kc < NKC; kc++) {
            __syncthreads();   // previous phase reads done
            // ---- stage weight chunk: split fp16 hi/lo + swizzle, on the fly ----
#pragma unroll
            for (int it = 0; it < 16; it++) {
                int id = it * 256 + tid;
                int n  = id >> 5;
                int j  = id & 31;
                int jj = j ^ ((n & 1) * 4);
                int cl = jj >> 2;
                int tt = jj & 3;
                int e0 = 128 * kc + 16 * cl + 2 * tt;
                const float* wp = cw + ((size_t)(fbase + n) * EIN + e0) * 3 + s;
                float v0 = wp[0];
                float v1 = wp[3];
                float v2 = wp[24];
                float v3 = wp[27];
                uint32_t h01, l01, h23, l23;
                split2h(v0, v1, h01, l01);
                split2h(v2, v3, h23, l23);
                smW[id] = make_uint4(h01, h23, l01, l23);
            }
            __syncthreads();

            // ---- build A fragments (fp16 hi/lo) for this (s, kc) ----
            uint32_t Ah[8][4], Al[8][4];
#pragma unroll
            for (int c = 0; c < 8; c++) {
                int e0 = 128 * kc + 16 * c + 2 * t;
                float2 x00 = m0 ? *(const float2*)(p0 + e0)     : make_float2(0.f, 0.f);
                float2 x01 = m1 ? *(const float2*)(p1 + e0)     : make_float2(0.f, 0.f);
                float2 x10 = m0 ? *(const float2*)(p0 + e0 + 8) : make_float2(0.f, 0.f);
                float2 x11 = m1 ? *(const float2*)(p1 + e0 + 8) : make_float2(0.f, 0.f);
                if (!FIRST) {
                    float a0 = aff_a_s[e0],     bA0 = aff_b_s[e0];
                    float a1 = aff_a_s[e0 + 1], bA1 = aff_b_s[e0 + 1];
                    float a8 = aff_a_s[e0 + 8], bA8 = aff_b_s[e0 + 8];
                    float a9 = aff_a_s[e0 + 9], bA9 = aff_b_s[e0 + 9];
                    if (m0) { x00.x = fmaf(a0, x00.x, bA0); x00.y = fmaf(a1, x00.y, bA1);
                              x10.x = fmaf(a8, x10.x, bA8); x10.y = fmaf(a9, x10.y, bA9); }
                    if (m1) { x01.x = fmaf(a0, x01.x, bA0); x01.y = fmaf(a1, x01.y, bA1);
                              x11.x = fmaf(a8, x11.x, bA8); x11.y = fmaf(a9, x11.y, bA9); }
                }
                split2h(x00.x, x00.y, Ah[c][0], Al[c][0]);
                split2h(x01.x, x01.y, Ah[c][1], Al[c][1]);
                split2h(x10.x, x10.y, Ah[c][2], Al[c][2]);
                split2h(x11.x, x11.y, Ah[c][3], Al[c][3]);
            }

            // ---- MMA: 8 ksteps x 16 ntiles x 3 terms ----
#pragma unroll
            for (int c = 0; c < 8; c++) {
                const int bslot = c * 4 + t;
#pragma unroll
                for (int nt = 0; nt < 16; nt++) {
                    const int n = nt * 8 + g;
                    uint4 f4 = smW[n * 32 + (bslot ^ ((n & 1) * 4))];
                    mma16816_f16(acc[nt], Ah[c], f4.x, f4.y);   // Ah*Wh
                    mma16816_f16(acc[nt], Ah[c], f4.z, f4.w);   // Ah*Wl
                    mma16816_f16(acc[nt], Al[c], f4.x, f4.y);   // Al*Wh
                }
            }
        }
    }

    // ---- epilogue: bias + lrelu, write act, fused BN partial stats ----
    float* out = dst ? g_act2 : g_act1;
#pragma unroll
    for (int nt = 0; nt < 16; nt++) {
        int col = nt * 8 + 2 * t;
        float bb0 = __ldg(cb + fbase + col);
        float bb1 = __ldg(cb + fbase + col + 1);
        float z0 = lrelu(acc[nt][0] + bb0);
        float z1 = lrelu(acc[nt][1] + bb1);
        float z2 = lrelu(acc[nt][2] + bb0);
        float z3 = lrelu(acc[nt][3] + bb1);
        *(float2*)(out + (size_t)r0 * F_ + fbase + col) = make_float2(z0, z1);
        *(float2*)(out + (size_t)r1 * F_ + fbase + col) = make_float2(z2, z3);
        float s0 = z0 + z2, s1 = z1 + z3;
        float q0 = z0 * z0 + z2 * z2, q1 = z1 * z1 + z3 * z3;
#pragma unroll
        for (int o = 4; o < 32; o <<= 1) {
            s0 += __shfl_xor_sync(0xffffffffu, s0, o);
            s1 += __shfl_xor_sync(0xffffffffu, s1, o);
            q0 += __shfl_xor_sync(0xffffffffu, q0, o);
            q1 += __shfl_xor_sync(0xffffffffu, q1, o);
        }
        if (g == 0) {
            s_sum[w * 128 + col]     = s0;
            s_sum[w * 128 + col + 1] = s1;
            s_sq [w * 128 + col]     = q0;
            s_sq [w * 128 + col + 1] = q1;
        }
    }
    __syncthreads();
    if (tid < 128) {
        float s = 0.f, q = 0.f;
#pragma unroll
        for (int ww = 0; ww < 8; ww++) {
            s += s_sum[ww * 128 + tid];
            q += s_sq [ww * 128 + tid];
        }
        g_csum [stat_layer][fbase + tid][tile] = s;
        g_csum2[stat_layer][fbase + tid][tile] = q;
    }
}

// =================================================================================
// A / C projections with fused hb, fused layer-4 affine, and pairwise weight
// packing folded in as blockIdx.y == 5.
// =================================================================================
constexpr int LT = 20;

__global__ void __launch_bounds__(256) ac_kernel(
    const float* __restrict__ W1, const float* __restrict__ b1,
    const float* __restrict__ h,
    const float* __restrict__ ga4, const float* __restrict__ be4,
    const float* __restrict__ W2, const float* __restrict__ W3,
    const float* __restrict__ W4)
{
    if (blockIdx.y == 5) {
        for (int idx = blockIdx.x * 256 + threadIdx.x; idx < 3 * 128 * 32;
             idx += 32 * 256) {
            int layer = idx >> 12;
            int rem   = idx & 4095;
            int n = rem >> 5;
            int s = rem & 31;
            int c = s >> 2;
            int t = s & 3;
            const float* W = layer == 0 ? W2 : (layer == 1 ? W3 : W4);
            uint32_t hw[2], lw[2];
#pragma unroll
            for (int j = 0; j < 2; j++) {
                int kw = 8 * c + 4 * j + t;
                float w0 = W[(size_t)(2 * kw) * 128 + n];
                float w1 = W[(size_t)(2 * kw + 1) * 128 + n];
                split2h(w0, w1, hw[j], lw[j]);
            }
            int slot = (c * 4 + t) ^ ((n & 1) * 4);
            g_wpack2[layer][n * 32 + slot] = make_uint4(hw[0], hw[1], lw[0], lw[1]);
        }
        return;
    }

    __shared__ float xf[LT][D_];
    __shared__ float aff_a_s[F_], aff_b_s[F_];
    __shared__ float hb_s[M_];

    const int b  = blockIdx.x;
    const int l0 = blockIdx.y * LT;
    const int t  = threadIdx.x;

    if (t < F_) {
        float s = 0.f, s2 = 0.f;
#pragma unroll
        for (int tt = 0; tt < RTILE; tt++) {
            s  += g_csum [3][t][tt];
            s2 += g_csum2[3][t][tt];
        }
        const float inv_n = 1.f / (float)NROW;
        float mean = s * inv_n;
        float var  = s2 * inv_n - mean * mean;
        float a = ga4[t] * rsqrtf(var + 1e-5f);
        aff_a_s[t] = a;
        aff_b_s[t] = be4[t] - mean * a;
    }
    __syncthreads();

    // build xf (act layout [row][ch], ch contiguous -> coalesced)
    for (int c = t; c < LT * D_; c += 256) {
        int ll = c / D_;
        int ch = c - ll * D_;
        int l  = l0 + ll;
        float v;
        if (ch < F_) {
            v = aff_a_s[ch] * g_act2[(size_t)(b * 100 + l) * F_ + ch] + aff_b_s[ch];
        } else if (ch == F_) {
            v = ((float)l / 10.0f - 2.0f) * 0.5f;
        } else {
            v = ((float)(l % 10) - 2.0f) * 0.5f;
        }
        xf[ll][ch] = v;
    }

    if (t < 128) {
        const float* Wc = W1 + (size_t)(2 * D_) * M_;
        const float* hrow = h + (size_t)b * E_;
        float acc = b1[t];
#pragma unroll 4
        for (int k = 0; k < E_; k++) acc += hrow[k] * Wc[(size_t)k * M_ + t];
        hb_s[t] = acc;
    }
    __syncthreads();

    const int n  = t & 127;
    const int lg = t >> 7;

    float accA[LT / 2], accC[LT / 2];
#pragma unroll
    for (int i = 0; i < LT / 2; i++) { accA[i] = 0.f; accC[i] = 0.f; }

    const float* Wa = W1;
    const float* Wb = W1 + (size_t)D_ * M_;
#pragma unroll 2
    for (int c = 0; c < D_; c++) {
        float wa = Wa[(size_t)c * M_ + n];
        float wb = Wb[(size_t)c * M_ + n];
#pragma unroll
        for (int i = 0; i < LT / 2; i++) {
            float x = xf[2 * i + lg][c];
            accA[i] += x * wa;
            accC[i] += x * wb;
        }
    }
    float hbv = hb_s[n];
#pragma unroll
    for (int i = 0; i < LT / 2; i++) {
        int l = l0 + 2 * i + lg;
        g_A[((size_t)b * L_ + l) * M_ + n] = accA[i];
        g_C[((size_t)b * L_ + l) * M_ + n] = accC[i] + hbv;
    }
}

// =================================================================================
// Tensor-core pairwise relation kernel — fp16 2-term split (R9, proven).
// =================================================================================
constexpr int SMEM_PW = 128 * 32 * 16;   // 65,536 B

DEV_INLINE void stageW(uint4* smW, int layer, int tid) {
    const uint4* src = g_wpack2[layer];
#pragma unroll
    for (int it = 0; it < 16; it++)
        smW[it * 256 + tid] = src[it * 256 + tid];
}

__global__ void __launch_bounds__(256) pairwise_mma(
    const float* __restrict__ b2, const float* __restrict__ b3,
    const float* __restrict__ b4)
{
    extern __shared__ char smraw[];
    uint4* smW    = (uint4*)smraw;
    float* s_part = (float*)smraw;

    const int tile = blockIdx.x;
    const int b    = blockIdx.y;
    const int row0 = tile * 128;
    const int tid  = threadIdx.x;
    const int w    = tid >> 5;
    const int lane = tid & 31;
    const int g    = lane >> 2;
    const int t    = lane & 3;

    uint32_t Ah[8][4];
    const int r0 = row0 + 16 * w + g;
    const int r1 = r0 + 8;
    {
        int rc0 = r0 < NPAIR ? r0 : 0;
        int rc1 = r1 < NPAIR ? r1 : 0;
        int i0 = rc0 / 100, j0 = rc0 - (rc0 / 100) * 100;
        int i1 = rc1 / 100, j1 = rc1 - (rc1 / 100) * 100;
        const float2* C0 = (const float2*)(g_C + ((size_t)b * L_ + i0) * M_);
        const float2* A0 = (const float2*)(g_A + ((size_t)b * L_ + j0) * M_);
        const float2* C1 = (const float2*)(g_C + ((size_t)b * L_ + i1) * M_);
        const float2* A1 = (const float2*)(g_A + ((size_t)b * L_ + j1) * M_);
#pragma unroll
        for (int c = 0; c < 8; c++) {
            int idx = 8 * c + t;
            float2 cc, aa;
            cc = C0[idx];     aa = A0[idx];
            Ah[c][0] = pack_h2(lrelu(cc.x + aa.x), lrelu(cc.y + aa.y));
            cc = C1[idx];     aa = A1[idx];
            Ah[c][1] = pack_h2(lrelu(cc.x + aa.x), lrelu(cc.y + aa.y));
            cc = C0[idx + 4]; aa = A0[idx + 4];
            Ah[c][2] = pack_h2(lrelu(cc.x + aa.x), lrelu(cc.y + aa.y));
            cc = C1[idx + 4]; aa = A1[idx + 4];
            Ah[c][3] = pack_h2(lrelu(cc.x + aa.x), lrelu(cc.y + aa.y));
        }
    }

    stageW(smW, 0, tid);
    __syncthreads();

#pragma unroll
    for (int layer = 0; layer < 3; layer++) {
        float acc[16][4];
#pragma unroll
        for (int nt = 0; nt < 16; nt++)
#pragma unroll
            for (int q = 0; q < 4; q++) acc[nt][q] = 0.f;

#pragma unroll
        for (int c = 0; c < 8; c++) {
            const int base_slot = c * 4 + t;
#pragma unroll
            for (int nt = 0; nt < 16; nt++) {
                const int n = nt * 8 + g;
                uint4 f4 = smW[n * 32 + (base_slot ^ ((n & 1) * 4))];
                mma16816_f16(acc[nt], Ah[c], f4.x, f4.y);
                mma16816_f16(acc[nt], Ah[c], f4.z, f4.w);
            }
        }

        if (layer < 2) {
            const float* bias = layer == 0 ? b2 : b3;
#pragma unroll
            for (int nt = 0; nt < 16; nt++) {
                int col = nt * 8 + 2 * t;
                float bb0 = __ldg(bias + col);
                float bb1 = __ldg(bias + col + 1);
                float z0 = lrelu(acc[nt][0] + bb0);
                float z1 = lrelu(acc[nt][1] + bb1);
                float z2 = lrelu(acc[nt][2] + bb0);
                float z3 = lrelu(acc[nt][3] + bb1);
                int c2  = nt >> 1;
                int off = (nt & 1) * 2;
                Ah[c2][off]     = pack_h2(z0, z1);
                Ah[c2][off + 1] = pack_h2(z2, z3);
            }
            __syncthreads();
            stageW(smW, layer + 1, tid);
            __syncthreads();
        } else {
            __syncthreads();
            const bool live0 = r0 < NPAIR;
            const bool live1 = r1 < NPAIR;
#pragma unroll
            for (int nt = 0; nt < 16; nt++) {
                int col = nt * 8 + 2 * t;
                float bb0 = __ldg(b4 + col);
                float bb1 = __ldg(b4 + col + 1);
                float z0 = live0 ? lrelu(acc[nt][0] + bb0) : 0.f;
                float z1 = live0 ? lrelu(acc[nt][1] + bb1) : 0.f;
                float z2 = live1 ? lrelu(acc[nt][2] + bb0) : 0.f;
                float z3 = live1 ? lrelu(acc[nt][3] + bb1) : 0.f;
                float v0 = z0 + z2;
                float v1 = z1 + z3;
#pragma unroll
                for (int o = 4; o < 32; o <<= 1) {
                    v0 += __shfl_xor_sync(0xffffffffu, v0, o);
                    v1 += __shfl_xor_sync(0xffffffffu, v1, o);
                }
                if (g == 0) {
                    s_part[w * 128 + col]     = v0;
                    s_part[w * 128 + col + 1] = v1;
                }
            }
            __syncthreads();
            if (tid < 128) {
                float ss = 0.f;
#pragma unroll
                for (int ww = 0; ww < 8; ww++) ss += s_part[ww * 128 + tid];
                g_part[((size_t)b * NTILE + tile) * M_ + tid] = ss;
            }
        }
    }
}

// =================================================================================
// Final decoder (unchanged)
// =================================================================================
__global__ void __launch_bounds__(128) final_kernel(
    const float* __restrict__ F1, const float* __restrict__ fb1,
    const float* __restrict__ F2, const float* __restrict__ fb2,
    float* __restrict__ out)
{
    const int b = blockIdx.x;
    const int t = threadIdx.x;
    __shared__ float s_s[M_], t_s[M_];

    float acc = 0.f;
    for (int i = 0; i < NTILE; i++)
        acc += g_part[((size_t)b * NTILE + i) * M_ + t];
    s_s[t] = acc;
    __syncthreads();

    float a2 = fb1[t];
#pragma unroll 4
    for (int k = 0; k < M_; k++) a2 += s_s[k] * F1[(size_t)k * M_ + t];
    t_s[t] = lrelu(a2);
    __syncthreads();

    for (int m = t; m < 512; m += 128) {
        float a3 = fb2[m];
#pragma unroll 4
        for (int k = 0; k < M_; k++) a3 += t_s[k] * F2[(size_t)k * 512 + m];
        out[(size_t)b * 512 + m] = lrelu(a3);
    }
}

// =================================================================================
// launcher — pairwise_mma stays launch #5 for ncu
// =================================================================================
extern "C" void kernel_launch(void* const* d_in, const int* in_sizes, int n_in,
                              void* d_out, int out_size)
{
    (void)in_sizes; (void)n_in; (void)out_size;

    const float* x   = (const float*)d_in[0];
    const float* h   = (const float*)d_in[1];
    const float* cw1 = (const float*)d_in[2];
    const float* cb1 = (const float*)d_in[3];
    const float* ga1 = (const float*)d_in[4];
    const float* be1 = (const float*)d_in[5];
    const float* cw2 = (const float*)d_in[6];
    const float* cb2 = (const float*)d_in[7];
    const float* ga2 = (const float*)d_in[8];
    const float* be2 = (const float*)d_in[9];
    const float* cw3 = (const float*)d_in[10];
    const float* cb3 = (const float*)d_in[11];
    const float* ga3 = (const float*)d_in[12];
    const float* be3 = (const float*)d_in[13];
    const float* cw4 = (const float*)d_in[14];
    const float* cb4 = (const float*)d_in[15];
    const float* ga4 = (const float*)d_in[16];
    const float* be4 = (const float*)d_in[17];
    const float* W1  = (const float*)d_in[18];
    const float* b1  = (const float*)d_in[19];
    const float* W2  = (const float*)d_in[20];
    const float* b2  = (const float*)d_in[21];
    const float* W3  = (const float*)d_in[22];
    const float* b3  = (const float*)d_in[23];
    const float* W4  = (const float*)d_in[24];
    const float* b4  = (const float*)d_in[25];
    const float* F1  = (const float*)d_in[26];
    const float* fb1 = (const float*)d_in[27];
    const float* F2  = (const float*)d_in[28];
    const float* fb2 = (const float*)d_in[29];
    float* out = (float*)d_out;

    cudaFuncSetAttribute(conv_mma<E_, true >,
                         cudaFuncAttributeMaxDynamicSharedMemorySize, CSMEM);
    cudaFuncSetAttribute(conv_mma<F_, false>,
                         cudaFuncAttributeMaxDynamicSharedMemorySize, CSMEM);
    cudaFuncSetAttribute(pairwise_mma,
                         cudaFuncAttributeMaxDynamicSharedMemorySize, SMEM_PW);

    dim3 cgrid(RTILE, 2);

    // 0..3: tensor-core conv stack with fused BN stats
    conv_mma<E_, true ><<<cgrid, 256, CSMEM>>>(x, 0, 0, nullptr, nullptr, cw1, cb1, 0, 0);
    conv_mma<F_, false><<<cgrid, 256, CSMEM>>>(nullptr, 0, 0, ga1, be1, cw2, cb2, 1, 1);
    conv_mma<F_, false><<<cgrid, 256, CSMEM>>>(nullptr, 1, 1, ga2, be2, cw3, cb3, 0, 2);
    conv_mma<F_, false><<<cgrid, 256, CSMEM>>>(nullptr, 0, 2, ga3, be3, cw4, cb4, 1, 3);

    // 4: projections (fused hb + layer-4 affine + pairwise weight packing)
    ac_kernel<<<dim3(B_, 6), 256>>>(W1, b1, h, ga4, be4, W2, W3, W4);

    // 5: tensor-core pairwise chain  <-- profiled by ncu -s 5 -c 1
    pairwise_mma<<<dim3(NTILE, B_), 256, SMEM_PW>>>(b2, b3, b4);

    // 6: decoder
    final_kernel<<<B_, 128>>>(F1, fb1, F2, fb2, out);
}

// round 12
// speedup vs baseline: 1.8491x; 1.1520x over previous
#include <cuda_runtime.h>
#include <cuda_fp16.h>
#include <cstdint>

#define DEV_INLINE __device__ __forceinline__

constexpr int L_   = 100;
constexpr int B_   = 32;
constexpr int E_   = 512;
constexpr int F_   = 256;
constexpr int M_   = 128;
constexpr int D_   = 258;
constexpr int NPAIR = L_ * L_;                 // 10000
constexpr int NTILE = (NPAIR + 127) / 128;     // 79
constexpr int NROW  = B_ * L_;                 // 3200 = 25 * 128
constexpr int RTILE = 25;

// packed conv-weight fragment array bases (uint4 units)
constexpr int CB0 = 0;                          // conv1: 4by*3s*4kc*2048
constexpr int CB1 = 98304;                      // conv2: 4by*3s*2kc*2048
constexpr int CB2 = 147456;
constexpr int CB3 = 196608;
constexpr int CWP_TOTAL = 245760;

// ---------------- scratch (device globals; no allocation allowed) ----------------
__device__ float g_act1[NROW * F_];
__device__ float g_act2[NROW * F_];
__device__ float g_csum [4][F_][32];
__device__ float g_csum2[4][F_][32];
__device__ float g_A[B_ * L_ * M_];
__device__ float g_C[B_ * L_ * M_];
__device__ float g_part[B_ * NTILE * M_];
__device__ __align__(16) uint4 g_wpack2[3][128 * 32];   // pairwise weights
__device__ __align__(16) uint4 g_cwp[CWP_TOTAL];        // conv weights (fragments)

DEV_INLINE float lrelu(float z) { return fmaxf(z, 0.f) + 0.1f * fminf(z, 0.f); }

DEV_INLINE uint32_t pack_h2(float x0, float x1) {
    __half2 h = __floats2half2_rn(x0, x1);
    return *reinterpret_cast<uint32_t*>(&h);
}

DEV_INLINE void split2h(float x0, float x1, uint32_t& hi, uint32_t& lo) {
    __half h0 = __float2half_rn(x0);
    __half h1 = __float2half_rn(x1);
    float r0 = x0 - __half2float(h0);
    float r1 = x1 - __half2float(h1);
    __half2 hh = __halves2half2(h0, h1);
    hi = *reinterpret_cast<uint32_t*>(&hh);
    lo = pack_h2(r0, r1);
}

DEV_INLINE void mma16816_f16(float c[4], const uint32_t a[4], uint32_t b0, uint32_t b1) {
    asm volatile(
        "mma.sync.aligned.m16n8k16.row.col.f32.f16.f16.f32 "
        "{%0,%1,%2,%3}, {%4,%5,%6,%7}, {%8,%9}, {%0,%1,%2,%3};"
        : "+f"(c[0]), "+f"(c[1]), "+f"(c[2]), "+f"(c[3])
        : "r"(a[0]), "r"(a[1]), "r"(a[2]), "r"(a[3]), "r"(b0), "r"(b1));
}

// =================================================================================
// One-time conv weight pack: raw conv weights -> fp16 hi/lo fragment uint4s,
// EXACTLY the layout the conv staging/MMA lookup expects.
//   index = base(layer) + (((by*3 + s)*NKC + kc) * 2048) + n*32 + j   (n<64, j<32)
//   content: jj = j ^ ((n&1)*4); e0 = 128*kc + 16*(jj>>2) + 2*(jj&3)
//            {h(e0,e0+1), h(e0+8,e0+9), l(e0,e0+1), l(e0+8,e0+9)} of W[(by*64+n)][e][s]
// =================================================================================
__global__ void __launch_bounds__(256) pack_conv(
    const float* __restrict__ cw1, const float* __restrict__ cw2,
    const float* __restrict__ cw3, const float* __restrict__ cw4)
{
    int idx = blockIdx.x * 256 + threadIdx.x;
    if (idx >= CWP_TOTAL) return;
    const float* cw; int EIN, NKC, rem;
    if (idx < CB1)      { rem = idx;       cw = cw1; EIN = 512; NKC = 4; }
    else if (idx < CB2) { rem = idx - CB1; cw = cw2; EIN = 256; NKC = 2; }
    else if (idx < CB3) { rem = idx - CB2; cw = cw3; EIN = 256; NKC = 2; }
    else                { rem = idx - CB3; cw = cw4; EIN = 256; NKC = 2; }
    int per_by = 3 * NKC * 2048;
    int by = rem / per_by;
    int r2 = rem - by * per_by;
    int s  = r2 / (NKC * 2048);
    int r3 = r2 - s * (NKC * 2048);
    int kc = r3 >> 11;
    int id = r3 & 2047;
    int n  = id >> 5;
    int j  = id & 31;
    int jj = j ^ ((n & 1) * 4);
    int e0 = 128 * kc + 16 * (jj >> 2) + 2 * (jj & 3);
    const float* wp = cw + ((size_t)(by * 64 + n) * EIN + e0) * 3 + s;
    float v0 = wp[0], v1 = wp[3], v2 = wp[24], v3 = wp[27];
    uint32_t h01, l01, h23, l23;
    split2h(v0, v1, h01, l01);
    split2h(v2, v3, h23, l23);
    g_cwp[idx] = make_uint4(h01, h23, l01, l23);
}

// =================================================================================
// Tensor-core Conv1d (K=3, pad 1) + bias + leakyReLU + fused BN stats.
// Grid (25 row tiles, 4 f-chunks of 64). 256 threads, warp = 16 rows x 64 cols.
// Weights staged by coalesced uint4 copy from g_cwp.
// =================================================================================
constexpr int CSMEM = 32768 + 4096 + 4096;

template <int EIN, bool FIRST>
__global__ void __launch_bounds__(256) conv_mma(
    const float* __restrict__ x_ext,
    int src, int prev_layer,
    const float* __restrict__ ga_prev, const float* __restrict__ be_prev,
    int wbase,                          // base index into g_cwp
    const float* __restrict__ cb,
    int dst, int stat_layer)
{
    constexpr int NKC = EIN / 128;
    extern __shared__ char smraw[];
    uint4*  smW     = (uint4*)smraw;                       // 2048 uint4 = 32KB
    float*  aff_a_s = (float*)(smraw + 32768);             // [EIN]
    float*  aff_b_s = aff_a_s + EIN;
    float*  s_sum   = (float*)(smraw + 32768 + 4096);      // [8][64]
    float*  s_sq    = s_sum + 512;

    const int tile = blockIdx.x;       // 0..24
    const int by   = blockIdx.y;       // 0..3
    const int f0   = by * 64;
    const int row0 = tile * 128;
    const int tid  = threadIdx.x;
    const int w    = tid >> 5;
    const int lane = tid & 31;
    const int g    = lane >> 2;
    const int t    = lane & 3;

    if (!FIRST) {
        for (int ch = tid; ch < EIN; ch += 256) {
            float s = 0.f, s2 = 0.f;
#pragma unroll
            for (int tt = 0; tt < RTILE; tt++) {
                s  += g_csum [prev_layer][ch][tt];
                s2 += g_csum2[prev_layer][ch][tt];
            }
            const float inv_n = 1.f / (float)NROW;
            float mean = s * inv_n;
            float var  = s2 * inv_n - mean * mean;
            float a = ga_prev[ch] * rsqrtf(var + 1e-5f);
            aff_a_s[ch] = a;
            aff_b_s[ch] = be_prev[ch] - mean * a;
        }
        __syncthreads();
    }

    const int r0 = row0 + 16 * w + g;
    const int r1 = r0 + 8;
    const int b0r = r0 / 100, l0r = r0 - b0r * 100;
    const int b1r = r1 / 100, l1r = r1 - b1r * 100;

    const float* act_in = src ? g_act2 : g_act1;

    float acc[8][4];
#pragma unroll
    for (int nt = 0; nt < 8; nt++)
#pragma unroll
        for (int q = 0; q < 4; q++) acc[nt][q] = 0.f;

#pragma unroll 1
    for (int s = 0; s < 3; s++) {
        const bool m0 = (unsigned)(l0r + s - 1) < 100u;
        const bool m1 = (unsigned)(l1r + s - 1) < 100u;
        const float* p0;
        const float* p1;
        if (FIRST) {
            p0 = x_ext + ((size_t)(m0 ? (l0r + s - 1) : 0) * B_ + b0r) * E_;
            p1 = x_ext + ((size_t)(m1 ? (l1r + s - 1) : 0) * B_ + b1r) * E_;
        } else {
            p0 = act_in + (size_t)(m0 ? (r0 + s - 1) : r0) * EIN;
            p1 = act_in + (size_t)(m1 ? (r1 + s - 1) : r1) * EIN;
        }

#pragma unroll 1
        for (int kc = 0; kc < NKC; kc++) {
            __syncthreads();
            // ---- coalesced weight staging from packed global ----
            {
                const uint4* srcW = g_cwp + wbase + (((by * 3 + s) * NKC + kc) << 11);
#pragma unroll
                for (int it = 0; it < 8; it++)
                    smW[it * 256 + tid] = srcW[it * 256 + tid];
            }
            __syncthreads();

            // ---- build A fragments (fp16 hi/lo) ----
            uint32_t Ah[8][4], Al[8][4];
#pragma unroll
            for (int c = 0; c < 8; c++) {
                int e0 = 128 * kc + 16 * c + 2 * t;
                float2 x00 = m0 ? *(const float2*)(p0 + e0)     : make_float2(0.f, 0.f);
                float2 x01 = m1 ? *(const float2*)(p1 + e0)     : make_float2(0.f, 0.f);
                float2 x10 = m0 ? *(const float2*)(p0 + e0 + 8) : make_float2(0.f, 0.f);
                float2 x11 = m1 ? *(const float2*)(p1 + e0 + 8) : make_float2(0.f, 0.f);
                if (!FIRST) {
                    float a0 = aff_a_s[e0],     bA0 = aff_b_s[e0];
                    float a1 = aff_a_s[e0 + 1], bA1 = aff_b_s[e0 + 1];
                    float a8 = aff_a_s[e0 + 8], bA8 = aff_b_s[e0 + 8];
                    float a9 = aff_a_s[e0 + 9], bA9 = aff_b_s[e0 + 9];
                    if (m0) { x00.x = fmaf(a0, x00.x, bA0); x00.y = fmaf(a1, x00.y, bA1);
                              x10.x = fmaf(a8, x10.x, bA8); x10.y = fmaf(a9, x10.y, bA9); }
                    if (m1) { x01.x = fmaf(a0, x01.x, bA0); x01.y = fmaf(a1, x01.y, bA1);
                              x11.x = fmaf(a8, x11.x, bA8); x11.y = fmaf(a9, x11.y, bA9); }
                }
                split2h(x00.x, x00.y, Ah[c][0], Al[c][0]);
                split2h(x01.x, x01.y, Ah[c][1], Al[c][1]);
                split2h(x10.x, x10.y, Ah[c][2], Al[c][2]);
                split2h(x11.x, x11.y, Ah[c][3], Al[c][3]);
            }

            // ---- MMA: 8 ksteps x 8 ntiles x 3 terms ----
#pragma unroll
            for (int c = 0; c < 8; c++) {
                const int bslot = c * 4 + t;
#pragma unroll
                for (int nt = 0; nt < 8; nt++) {
                    const int n = nt * 8 + g;
                    uint4 f4 = smW[n * 32 + (bslot ^ ((n & 1) * 4))];
                    mma16816_f16(acc[nt], Ah[c], f4.x, f4.y);
                    mma16816_f16(acc[nt], Ah[c], f4.z, f4.w);
                    mma16816_f16(acc[nt], Al[c], f4.x, f4.y);
                }
            }
        }
    }

    // ---- epilogue: bias + lrelu, write act, fused BN partial stats ----
    float* out = dst ? g_act2 : g_act1;
#pragma unroll
    for (int nt = 0; nt < 8; nt++) {
        int col = nt * 8 + 2 * t;
        float bb0 = __ldg(cb + f0 + col);
        float bb1 = __ldg(cb + f0 + col + 1);
        float z0 = lrelu(acc[nt][0] + bb0);
        float z1 = lrelu(acc[nt][1] + bb1);
        float z2 = lrelu(acc[nt][2] + bb0);
        float z3 = lrelu(acc[nt][3] + bb1);
        *(float2*)(out + (size_t)r0 * F_ + f0 + col) = make_float2(z0, z1);
        *(float2*)(out + (size_t)r1 * F_ + f0 + col) = make_float2(z2, z3);
        float s0 = z0 + z2, s1 = z1 + z3;
        float q0 = z0 * z0 + z2 * z2, q1 = z1 * z1 + z3 * z3;
#pragma unroll
        for (int o = 4; o < 32; o <<= 1) {
            s0 += __shfl_xor_sync(0xffffffffu, s0, o);
            s1 += __shfl_xor_sync(0xffffffffu, s1, o);
            q0 += __shfl_xor_sync(0xffffffffu, q0, o);
            q1 += __shfl_xor_sync(0xffffffffu, q1, o);
        }
        if (g == 0) {
            s_sum[w * 64 + col]     = s0;
            s_sum[w * 64 + col + 1] = s1;
            s_sq [w * 64 + col]     = q0;
            s_sq [w * 64 + col + 1] = q1;
        }
    }
    __syncthreads();
    if (tid < 64) {
        float s = 0.f, q = 0.f;
#pragma unroll
        for (int ww = 0; ww < 8; ww++) {
            s += s_sum[ww * 64 + tid];
            q += s_sq [ww * 64 + tid];
        }
        g_csum [stat_layer][f0 + tid][tile] = s;
        g_csum2[stat_layer][f0 + tid][tile] = q;
    }
}

// =================================================================================
// A / C projections with fused hb, fused layer-4 affine, and pairwise weight
// packing folded in as blockIdx.y == 5.
// =================================================================================
constexpr int LT = 20;

__global__ void __launch_bounds__(256) ac_kernel(
    const float* __restrict__ W1, const float* __restrict__ b1,
    const float* __restrict__ h,
    const float* __restrict__ ga4, const float* __restrict__ be4,
    const float* __restrict__ W2, const float* __restrict__ W3,
    const float* __restrict__ W4)
{
    if (blockIdx.y == 5) {
        for (int idx = blockIdx.x * 256 + threadIdx.x; idx < 3 * 128 * 32;
             idx += 32 * 256) {
            int layer = idx >> 12;
            int rem   = idx & 4095;
            int n = rem >> 5;
            int s = rem & 31;
            int c = s >> 2;
            int t = s & 3;
            const float* W = layer == 0 ? W2 : (layer == 1 ? W3 : W4);
            uint32_t hw[2], lw[2];
#pragma unroll
            for (int j = 0; j < 2; j++) {
                int kw = 8 * c + 4 * j + t;
                float w0 = W[(size_t)(2 * kw) * 128 + n];
                float w1 = W[(size_t)(2 * kw + 1) * 128 + n];
                split2h(w0, w1, hw[j], lw[j]);
            }
            int slot = (c * 4 + t) ^ ((n & 1) * 4);
            g_wpack2[layer][n * 32 + slot] = make_uint4(hw[0], hw[1], lw[0], lw[1]);
        }
        return;
    }

    __shared__ float xf[LT][D_];
    __shared__ float aff_a_s[F_], aff_b_s[F_];
    __shared__ float hb_s[M_];

    const int b  = blockIdx.x;
    const int l0 = blockIdx.y * LT;
    const int t  = threadIdx.x;

    if (t < F_) {
        float s = 0.f, s2 = 0.f;
#pragma unroll
        for (int tt = 0; tt < RTILE; tt++) {
            s  += g_csum [3][t][tt];
            s2 += g_csum2[3][t][tt];
        }
        const float inv_n = 1.f / (float)NROW;
        float mean = s * inv_n;
        float var  = s2 * inv_n - mean * mean;
        float a = ga4[t] * rsqrtf(var + 1e-5f);
        aff_a_s[t] = a;
        aff_b_s[t] = be4[t] - mean * a;
    }
    __syncthreads();

    for (int c = t; c < LT * D_; c += 256) {
        int ll = c / D_;
        int ch = c - ll * D_;
        int l  = l0 + ll;
        float v;
        if (ch < F_) {
            v = aff_a_s[ch] * g_act2[(size_t)(b * 100 + l) * F_ + ch] + aff_b_s[ch];
        } else if (ch == F_) {
            v = ((float)l / 10.0f - 2.0f) * 0.5f;
        } else {
            v = ((float)(l % 10) - 2.0f) * 0.5f;
        }
        xf[ll][ch] = v;
    }

    if (t < 128) {
        const float* Wc = W1 + (size_t)(2 * D_) * M_;
        const float* hrow = h + (size_t)b * E_;
        float acc = b1[t];
#pragma unroll 4
        for (int k = 0; k < E_; k++) acc += hrow[k] * Wc[(size_t)k * M_ + t];
        hb_s[t] = acc;
    }
    __syncthreads();

    const int n  = t & 127;
    const int lg = t >> 7;

    float accA[LT / 2], accC[LT / 2];
#pragma unroll
    for (int i = 0; i < LT / 2; i++) { accA[i] = 0.f; accC[i] = 0.f; }

    const float* Wa = W1;
    const float* Wb = W1 + (size_t)D_ * M_;
#pragma unroll 2
    for (int c = 0; c < D_; c++) {
        float wa = Wa[(size_t)c * M_ + n];
        float wb = Wb[(size_t)c * M_ + n];
#pragma unroll
        for (int i = 0; i < LT / 2; i++) {
            float x = xf[2 * i + lg][c];
            accA[i] += x * wa;
            accC[i] += x * wb;
        }
    }
    float hbv = hb_s[n];
#pragma unroll
    for (int i = 0; i < LT / 2; i++) {
        int l = l0 + 2 * i + lg;
        g_A[((size_t)b * L_ + l) * M_ + n] = accA[i];
        g_C[((size_t)b * L_ + l) * M_ + n] = accC[i] + hbv;
    }
}

// =================================================================================
// Tensor-core pairwise relation kernel — fp16 2-term split (R9, proven).
// =================================================================================
constexpr int SMEM_PW = 128 * 32 * 16;

DEV_INLINE void stageW(uint4* smW, int layer, int tid) {
    const uint4* src = g_wpack2[layer];
#pragma unroll
    for (int it = 0; it < 16; it++)
        smW[it * 256 + tid] = src[it * 256 + tid];
}

__global__ void __launch_bounds__(256) pairwise_mma(
    const float* __restrict__ b2, const float* __restrict__ b3,
    const float* __restrict__ b4)
{
    extern __shared__ char smraw[];
    uint4* smW    = (uint4*)smraw;
    float* s_part = (float*)smraw;

    const int tile = blockIdx.x;
    const int b    = blockIdx.y;
    const int row0 = tile * 128;
    const int tid  = threadIdx.x;
    const int w    = tid >> 5;
    const int lane = tid & 31;
    const int g    = lane >> 2;
    const int t    = lane & 3;

    uint32_t Ah[8][4];
    const int r0 = row0 + 16 * w + g;
    const int r1 = r0 + 8;
    {
        int rc0 = r0 < NPAIR ? r0 : 0;
        int rc1 = r1 < NPAIR ? r1 : 0;
        int i0 = rc0 / 100, j0 = rc0 - (rc0 / 100) * 100;
        int i1 = rc1 / 100, j1 = rc1 - (rc1 / 100) * 100;
        const float2* C0 = (const float2*)(g_C + ((size_t)b * L_ + i0) * M_);
        const float2* A0 = (const float2*)(g_A + ((size_t)b * L_ + j0) * M_);
        const float2* C1 = (const float2*)(g_C + ((size_t)b * L_ + i1) * M_);
        const float2* A1 = (const float2*)(g_A + ((size_t)b * L_ + j1) * M_);
#pragma unroll
        for (int c = 0; c < 8; c++) {
            int idx = 8 * c + t;
            float2 cc, aa;
            cc = C0[idx];     aa = A0[idx];
            Ah[c][0] = pack_h2(lrelu(cc.x + aa.x), lrelu(cc.y + aa.y));
            cc = C1[idx];     aa = A1[idx];
            Ah[c][1] = pack_h2(lrelu(cc.x + aa.x), lrelu(cc.y + aa.y));
            cc = C0[idx + 4]; aa = A0[idx + 4];
            Ah[c][2] = pack_h2(lrelu(cc.x + aa.x), lrelu(cc.y + aa.y));
            cc = C1[idx + 4]; aa = A1[idx + 4];
            Ah[c][3] = pack_h2(lrelu(cc.x + aa.x), lrelu(cc.y + aa.y));
        }
    }

    stageW(smW, 0, tid);
    __syncthreads();

#pragma unroll
    for (int layer = 0; layer < 3; layer++) {
        float acc[16][4];
#pragma unroll
        for (int nt = 0; nt < 16; nt++)
#pragma unroll
            for (int q = 0; q < 4; q++) acc[nt][q] = 0.f;

#pragma unroll
        for (int c = 0; c < 8; c++) {
            const int base_slot = c * 4 + t;
#pragma unroll
            for (int nt = 0; nt < 16; nt++) {
                const int n = nt * 8 + g;
                uint4 f4 = smW[n * 32 + (base_slot ^ ((n & 1) * 4))];
                mma16816_f16(acc[nt], Ah[c], f4.x, f4.y);
                mma16816_f16(acc[nt], Ah[c], f4.z, f4.w);
            }
        }

        if (layer < 2) {
            const float* bias = layer == 0 ? b2 : b3;
#pragma unroll
            for (int nt = 0; nt < 16; nt++) {
                int col = nt * 8 + 2 * t;
                float bb0 = __ldg(bias + col);
                float bb1 = __ldg(bias + col + 1);
                float z0 = lrelu(acc[nt][0] + bb0);
                float z1 = lrelu(acc[nt][1] + bb1);
                float z2 = lrelu(acc[nt][2] + bb0);
                float z3 = lrelu(acc[nt][3] + bb1);
                int c2  = nt >> 1;
                int off = (nt & 1) * 2;
                Ah[c2][off]     = pack_h2(z0, z1);
                Ah[c2][off + 1] = pack_h2(z2, z3);
            }
            __syncthreads();
            stageW(smW, layer + 1, tid);
            __syncthreads();
        } else {
            __syncthreads();
            const bool live0 = r0 < NPAIR;
            const bool live1 = r1 < NPAIR;
#pragma unroll
            for (int nt = 0; nt < 16; nt++) {
                int col = nt * 8 + 2 * t;
                float bb0 = __ldg(b4 + col);
                float bb1 = __ldg(b4 + col + 1);
                float z0 = live0 ? lrelu(acc[nt][0] + bb0) : 0.f;
                float z1 = live0 ? lrelu(acc[nt][1] + bb1) : 0.f;
                float z2 = live1 ? lrelu(acc[nt][2] + bb0) : 0.f;
                float z3 = live1 ? lrelu(acc[nt][3] + bb1) : 0.f;
                float v0 = z0 + z2;
                float v1 = z1 + z3;
#pragma unroll
                for (int o = 4; o < 32; o <<= 1) {
                    v0 += __shfl_xor_sync(0xffffffffu, v0, o);
                    v1 += __shfl_xor_sync(0xffffffffu, v1, o);
                }
                if (g == 0) {
                    s_part[w * 128 + col]     = v0;
                    s_part[w * 128 + col + 1] = v1;
                }
            }
            __syncthreads();
            if (tid < 128) {
                float ss = 0.f;
#pragma unroll
                for (int ww = 0; ww < 8; ww++) ss += s_part[ww * 128 + tid];
                g_part[((size_t)b * NTILE + tile) * M_ + tid] = ss;
            }
        }
    }
}

// =================================================================================
// Final decoder (unchanged)
// =================================================================================
__global__ void __launch_bounds__(128) final_kernel(
    const float* __restrict__ F1, const float* __restrict__ fb1,
    const float* __restrict__ F2, const float* __restrict__ fb2,
    float* __restrict__ out)
{
    const int b = blockIdx.x;
    const int t = threadIdx.x;
    __shared__ float s_s[M_], t_s[M_];

    float acc = 0.f;
    for (int i = 0; i < NTILE; i++)
        acc += g_part[((size_t)b * NTILE + i) * M_ + t];
    s_s[t] = acc;
    __syncthreads();

    float a2 = fb1[t];
#pragma unroll 4
    for (int k = 0; k < M_; k++) a2 += s_s[k] * F1[(size_t)k * M_ + t];
    t_s[t] = lrelu(a2);
    __syncthreads();

    for (int m = t; m < 512; m += 128) {
        float a3 = fb2[m];
#pragma unroll 4
        for (int k = 0; k < M_; k++) a3 += t_s[k] * F2[(size_t)k * 512 + m];
        out[(size_t)b * 512 + m] = lrelu(a3);
    }
}

// =================================================================================
// launcher
// =================================================================================
extern "C" void kernel_launch(void* const* d_in, const int* in_sizes, int n_in,
                              void* d_out, int out_size)
{
    (void)in_sizes; (void)n_in; (void)out_size;

    const float* x   = (const float*)d_in[0];
    const float* h   = (const float*)d_in[1];
    const float* cw1 = (const float*)d_in[2];
    const float* cb1 = (const float*)d_in[3];
    const float* ga1 = (const float*)d_in[4];
    const float* be1 = (const float*)d_in[5];
    const float* cw2 = (const float*)d_in[6];
    const float* cb2 = (const float*)d_in[7];
    const float* ga2 = (const float*)d_in[8];
    const float* be2 = (const float*)d_in[9];
    const float* cw3 = (const float*)d_in[10];
    const float* cb3 = (const float*)d_in[11];
    const float* ga3 = (const float*)d_in[12];
    const float* be3 = (const float*)d_in[13];
    const float* cw4 = (const float*)d_in[14];
    const float* cb4 = (const float*)d_in[15];
    const float* ga4 = (const float*)d_in[16];
    const float* be4 = (const float*)d_in[17];
    const float* W1  = (const float*)d_in[18];
    const float* b1  = (const float*)d_in[19];
    const float* W2  = (const float*)d_in[20];
    const float* b2  = (const float*)d_in[21];
    const float* W3  = (const float*)d_in[22];
    const float* b3  = (const float*)d_in[23];
    const float* W4  = (const float*)d_in[24];
    const float* b4  = (const float*)d_in[25];
    const float* F1  = (const float*)d_in[26];
    const float* fb1 = (const float*)d_in[27];
    const float* F2  = (const float*)d_in[28];
    const float* fb2 = (const float*)d_in[29];
    float* out = (float*)d_out;

    cudaFuncSetAttribute(conv_mma<E_, true >,
                         cudaFuncAttributeMaxDynamicSharedMemorySize, CSMEM);
    cudaFuncSetAttribute(conv_mma<F_, false>,
                         cudaFuncAttributeMaxDynamicSharedMemorySize, CSMEM);
    cudaFuncSetAttribute(pairwise_mma,
                         cudaFuncAttributeMaxDynamicSharedMemorySize, SMEM_PW);

    dim3 cgrid(RTILE, 4);

    // 0: one-time conv weight pack
    pack_conv<<<(CWP_TOTAL + 255) / 256, 256>>>(cw1, cw2, cw3, cw4);

    // 1..4: tensor-core conv stack with fused BN stats
    conv_mma<E_, true ><<<cgrid, 256, CSMEM>>>(x, 0, 0, nullptr, nullptr, CB0, cb1, 0, 0);
    conv_mma<F_, false><<<cgrid, 256, CSMEM>>>(nullptr, 0, 0, ga1, be1, CB1, cb2, 1, 1);
    conv_mma<F_, false><<<cgrid, 256, CSMEM>>>(nullptr, 1, 1, ga2, be2, CB2, cb3, 0, 2);
    conv_mma<F_, false><<<cgrid, 256, CSMEM>>>(nullptr, 0, 2, ga3, be3, CB3, cb4, 1, 3);

    // 5: projections  <-- profiled by ncu -s 5 -c 1
    ac_kernel<<<dim3(B_, 6), 256>>>(W1, b1, h, ga4, be4, W2, W3, W4);

    // 6: tensor-core pairwise chain
    pairwise_mma<<<dim3(NTILE, B_), 256, SMEM_PW>>>(b2, b3, b4);

    // 7: decoder
    final_kernel<<<B_, 128>>>(F1, fb1, F2, fb2, out);
}

// round 13
// speedup vs baseline: 2.0718x; 1.1204x over previous
#include <cuda_runtime.h>
#include <cuda_fp16.h>
#include <cstdint>

#define DEV_INLINE __device__ __forceinline__

constexpr int L_   = 100;
constexpr int B_   = 32;
constexpr int E_   = 512;
constexpr int F_   = 256;
constexpr int M_   = 128;
constexpr int D_   = 258;
constexpr int NPAIR = L_ * L_;                 // 10000
constexpr int NTILE = (NPAIR + 127) / 128;     // 79
constexpr int NROW  = B_ * L_;                 // 3200 = 25 * 128
constexpr int RTILE = 25;

// packed conv-weight fragment array bases (uint4 units)
constexpr int CB0 = 0;                          // conv1: 4by*3s*4kc*2048
constexpr int CB1 = 98304;                      // conv2: 4by*3s*2kc*2048
constexpr int CB2 = 147456;
constexpr int CB3 = 196608;
constexpr int CWP_TOTAL = 245760;

// ---------------- scratch (device globals; no allocation allowed) ----------------
__device__ float g_act1[NROW * F_];
__device__ float g_act2[NROW * F_];
__device__ float g_csum [4][F_][32];
__device__ float g_csum2[4][F_][32];
__device__ float g_A[B_ * L_ * M_];
__device__ float g_C[B_ * L_ * M_];
__device__ float g_part[B_ * NTILE * M_];
__device__ __align__(16) uint4 g_wpack2[3][128 * 32];   // pairwise weights
__device__ __align__(16) uint4 g_cwp[CWP_TOTAL];        // conv weights (fragments)

DEV_INLINE float lrelu(float z) { return fmaxf(z, 0.f) + 0.1f * fminf(z, 0.f); }

DEV_INLINE uint32_t pack_h2(float x0, float x1) {
    __half2 h = __floats2half2_rn(x0, x1);
    return *reinterpret_cast<uint32_t*>(&h);
}

DEV_INLINE void split2h(float x0, float x1, uint32_t& hi, uint32_t& lo) {
    __half h0 = __float2half_rn(x0);
    __half h1 = __float2half_rn(x1);
    float r0 = x0 - __half2float(h0);
    float r1 = x1 - __half2float(h1);
    __half2 hh = __halves2half2(h0, h1);
    hi = *reinterpret_cast<uint32_t*>(&hh);
    lo = pack_h2(r0, r1);
}

DEV_INLINE void mma16816_f16(float c[4], const uint32_t a[4], uint32_t b0, uint32_t b1) {
    asm volatile(
        "mma.sync.aligned.m16n8k16.row.col.f32.f16.f16.f32 "
        "{%0,%1,%2,%3}, {%4,%5,%6,%7}, {%8,%9}, {%0,%1,%2,%3};"
        : "+f"(c[0]), "+f"(c[1]), "+f"(c[2]), "+f"(c[3])
        : "r"(a[0]), "r"(a[1]), "r"(a[2]), "r"(a[3]), "r"(b0), "r"(b1));
}

// =================================================================================
// One-time conv weight pack (fp16 hi/lo fragment uint4s; layout matches conv MMA).
// =================================================================================
__global__ void __launch_bounds__(256) pack_conv(
    const float* __restrict__ cw1, const float* __restrict__ cw2,
    const float* __restrict__ cw3, const float* __restrict__ cw4)
{
    int idx = blockIdx.x * 256 + threadIdx.x;
    if (idx >= CWP_TOTAL) return;
    const float* cw; int EIN, NKC, rem;
    if (idx < CB1)      { rem = idx;       cw = cw1; EIN = 512; NKC = 4; }
    else if (idx < CB2) { rem = idx - CB1; cw = cw2; EIN = 256; NKC = 2; }
    else if (idx < CB3) { rem = idx - CB2; cw = cw3; EIN = 256; NKC = 2; }
    else                { rem = idx - CB3; cw = cw4; EIN = 256; NKC = 2; }
    int per_by = 3 * NKC * 2048;
    int by = rem / per_by;
    int r2 = rem - by * per_by;
    int s  = r2 / (NKC * 2048);
    int r3 = r2 - s * (NKC * 2048);
    int kc = r3 >> 11;
    int id = r3 & 2047;
    int n  = id >> 5;
    int j  = id & 31;
    int jj = j ^ ((n & 1) * 4);
    int e0 = 128 * kc + 16 * (jj >> 2) + 2 * (jj & 3);
    const float* wp = cw + ((size_t)(by * 64 + n) * EIN + e0) * 3 + s;
    float v0 = wp[0], v1 = wp[3], v2 = wp[24], v3 = wp[27];
    uint32_t h01, l01, h23, l23;
    split2h(v0, v1, h01, l01);
    split2h(v2, v3, h23, l23);
    g_cwp[idx] = make_uint4(h01, h23, l01, l23);
}

// =================================================================================
// Tensor-core Conv1d (K=3, pad 1) + bias + leakyReLU + fused BN stats.
// 2-term fp16: acc = Ah*Wh + Ah*Wl = Ah*W (W split exact; activation rounded).
// __launch_bounds__(256, 2): 2 blocks/SM for cross-block MMA/ALU overlap.
// =================================================================================
constexpr int CSMEM = 32768 + 4096 + 4096;

template <int EIN, bool FIRST>
__global__ void __launch_bounds__(256, 2) conv_mma(
    const float* __restrict__ x_ext,
    int src, int prev_layer,
    const float* __restrict__ ga_prev, const float* __restrict__ be_prev,
    int wbase,
    const float* __restrict__ cb,
    int dst, int stat_layer)
{
    constexpr int NKC = EIN / 128;
    extern __shared__ char smraw[];
    uint4*  smW     = (uint4*)smraw;                       // 2048 uint4 = 32KB
    float*  aff_a_s = (float*)(smraw + 32768);             // [EIN]
    float*  aff_b_s = aff_a_s + EIN;
    float*  s_sum   = (float*)(smraw + 32768 + 4096);      // [8][64]
    float*  s_sq    = s_sum + 512;

    const int tile = blockIdx.x;       // 0..24
    const int by   = blockIdx.y;       // 0..3
    const int f0   = by * 64;
    const int row0 = tile * 128;
    const int tid  = threadIdx.x;
    const int w    = tid >> 5;
    const int lane = tid & 31;
    const int g    = lane >> 2;
    const int t    = lane & 3;

    if (!FIRST) {
        for (int ch = tid; ch < EIN; ch += 256) {
            float s = 0.f, s2 = 0.f;
#pragma unroll
            for (int tt = 0; tt < RTILE; tt++) {
                s  += g_csum [prev_layer][ch][tt];
                s2 += g_csum2[prev_layer][ch][tt];
            }
            const float inv_n = 1.f / (float)NROW;
            float mean = s * inv_n;
            float var  = s2 * inv_n - mean * mean;
            float a = ga_prev[ch] * rsqrtf(var + 1e-5f);
            aff_a_s[ch] = a;
            aff_b_s[ch] = be_prev[ch] - mean * a;
        }
        __syncthreads();
    }

    const int r0 = row0 + 16 * w + g;
    const int r1 = r0 + 8;
    const int b0r = r0 / 100, l0r = r0 - b0r * 100;
    const int b1r = r1 / 100, l1r = r1 - b1r * 100;

    const float* act_in = src ? g_act2 : g_act1;

    float acc[8][4];
#pragma unroll
    for (int nt = 0; nt < 8; nt++)
#pragma unroll
        for (int q = 0; q < 4; q++) acc[nt][q] = 0.f;

#pragma unroll 1
    for (int s = 0; s < 3; s++) {
        const bool m0 = (unsigned)(l0r + s - 1) < 100u;
        const bool m1 = (unsigned)(l1r + s - 1) < 100u;
        const float* p0;
        const float* p1;
        if (FIRST) {
            p0 = x_ext + ((size_t)(m0 ? (l0r + s - 1) : 0) * B_ + b0r) * E_;
            p1 = x_ext + ((size_t)(m1 ? (l1r + s - 1) : 0) * B_ + b1r) * E_;
        } else {
            p0 = act_in + (size_t)(m0 ? (r0 + s - 1) : r0) * EIN;
            p1 = act_in + (size_t)(m1 ? (r1 + s - 1) : r1) * EIN;
        }

#pragma unroll 1
        for (int kc = 0; kc < NKC; kc++) {
            __syncthreads();
            {
                const uint4* srcW = g_cwp + wbase + (((by * 3 + s) * NKC + kc) << 11);
#pragma unroll
                for (int it = 0; it < 8; it++)
                    smW[it * 256 + tid] = srcW[it * 256 + tid];
            }
            __syncthreads();

            // ---- build A fragments (single fp16, rounded) ----
            uint32_t Ah[8][4];
#pragma unroll
            for (int c = 0; c < 8; c++) {
                int e0 = 128 * kc + 16 * c + 2 * t;
                float2 x00 = m0 ? *(const float2*)(p0 + e0)     : make_float2(0.f, 0.f);
                float2 x01 = m1 ? *(const float2*)(p1 + e0)     : make_float2(0.f, 0.f);
                float2 x10 = m0 ? *(const float2*)(p0 + e0 + 8) : make_float2(0.f, 0.f);
                float2 x11 = m1 ? *(const float2*)(p1 + e0 + 8) : make_float2(0.f, 0.f);
                if (!FIRST) {
                    float a0 = aff_a_s[e0],     bA0 = aff_b_s[e0];
                    float a1 = aff_a_s[e0 + 1], bA1 = aff_b_s[e0 + 1];
                    float a8 = aff_a_s[e0 + 8], bA8 = aff_b_s[e0 + 8];
                    float a9 = aff_a_s[e0 + 9], bA9 = aff_b_s[e0 + 9];
                    if (m0) { x00.x = fmaf(a0, x00.x, bA0); x00.y = fmaf(a1, x00.y, bA1);
                              x10.x = fmaf(a8, x10.x, bA8); x10.y = fmaf(a9, x10.y, bA9); }
                    if (m1) { x01.x = fmaf(a0, x01.x, bA0); x01.y = fmaf(a1, x01.y, bA1);
                              x11.x = fmaf(a8, x11.x, bA8); x11.y = fmaf(a9, x11.y, bA9); }
                }
                Ah[c][0] = pack_h2(x00.x, x00.y);
                Ah[c][1] = pack_h2(x01.x, x01.y);
                Ah[c][2] = pack_h2(x10.x, x10.y);
                Ah[c][3] = pack_h2(x11.x, x11.y);
            }

            // ---- MMA: 8 ksteps x 8 ntiles x 2 terms ----
#pragma unroll
            for (int c = 0; c < 8; c++) {
                const int bslot = c * 4 + t;
#pragma unroll
                for (int nt = 0; nt < 8; nt++) {
                    const int n = nt * 8 + g;
                    uint4 f4 = smW[n * 32 + (bslot ^ ((n & 1) * 4))];
                    mma16816_f16(acc[nt], Ah[c], f4.x, f4.y);
                    mma16816_f16(acc[nt], Ah[c], f4.z, f4.w);
                }
            }
        }
    }

    // ---- epilogue: bias + lrelu, write act, fused BN partial stats ----
    float* out = dst ? g_act2 : g_act1;
#pragma unroll
    for (int nt = 0; nt < 8; nt++) {
        int col = nt * 8 + 2 * t;
        float bb0 = __ldg(cb + f0 + col);
        float bb1 = __ldg(cb + f0 + col + 1);
        float z0 = lrelu(acc[nt][0] + bb0);
        float z1 = lrelu(acc[nt][1] + bb1);
        float z2 = lrelu(acc[nt][2] + bb0);
        float z3 = lrelu(acc[nt][3] + bb1);
        *(float2*)(out + (size_t)r0 * F_ + f0 + col) = make_float2(z0, z1);
        *(float2*)(out + (size_t)r1 * F_ + f0 + col) = make_float2(z2, z3);
        float s0 = z0 + z2, s1 = z1 + z3;
        float q0 = z0 * z0 + z2 * z2, q1 = z1 * z1 + z3 * z3;
#pragma unroll
        for (int o = 4; o < 32; o <<= 1) {
            s0 += __shfl_xor_sync(0xffffffffu, s0, o);
            s1 += __shfl_xor_sync(0xffffffffu, s1, o);
            q0 += __shfl_xor_sync(0xffffffffu, q0, o);
            q1 += __shfl_xor_sync(0xffffffffu, q1, o);
        }
        if (g == 0) {
            s_sum[w * 64 + col]     = s0;
            s_sum[w * 64 + col + 1] = s1;
            s_sq [w * 64 + col]     = q0;
            s_sq [w * 64 + col + 1] = q1;
        }
    }
    __syncthreads();
    if (tid < 64) {
        float s = 0.f, q = 0.f;
#pragma unroll
        for (int ww = 0; ww < 8; ww++) {
            s += s_sum[ww * 64 + tid];
            q += s_sq [ww * 64 + tid];
        }
        g_csum [stat_layer][f0 + tid][tile] = s;
        g_csum2[stat_layer][f0 + tid][tile] = q;
    }
}

// =================================================================================
// A / C projections with fused hb, layer-4 affine, and pairwise weight packing.
// =================================================================================
constexpr int LT = 20;

__global__ void __launch_bounds__(256) ac_kernel(
    const float* __restrict__ W1, const float* __restrict__ b1,
    const float* __restrict__ h,
    const float* __restrict__ ga4, const float* __restrict__ be4,
    const float* __restrict__ W2, const float* __restrict__ W3,
    const float* __restrict__ W4)
{
    if (blockIdx.y == 5) {
        for (int idx = blockIdx.x * 256 + threadIdx.x; idx < 3 * 128 * 32;
             idx += 32 * 256) {
            int layer = idx >> 12;
            int rem   = idx & 4095;
            int n = rem >> 5;
            int s = rem & 31;
            int c = s >> 2;
            int t = s & 3;
            const float* W = layer == 0 ? W2 : (layer == 1 ? W3 : W4);
            uint32_t hw[2], lw[2];
#pragma unroll
            for (int j = 0; j < 2; j++) {
                int kw = 8 * c + 4 * j + t;
                float w0 = W[(size_t)(2 * kw) * 128 + n];
                float w1 = W[(size_t)(2 * kw + 1) * 128 + n];
                split2h(w0, w1, hw[j], lw[j]);
            }
            int slot = (c * 4 + t) ^ ((n & 1) * 4);
            g_wpack2[layer][n * 32 + slot] = make_uint4(hw[0], hw[1], lw[0], lw[1]);
        }
        return;
    }

    __shared__ float xf[LT][D_];
    __shared__ float aff_a_s[F_], aff_b_s[F_];
    __shared__ float hb_s[M_];

    const int b  = blockIdx.x;
    const int l0 = blockIdx.y * LT;
    const int t  = threadIdx.x;

    if (t < F_) {
        float s = 0.f, s2 = 0.f;
#pragma unroll
        for (int tt = 0; tt < RTILE; tt++) {
            s  += g_csum [3][t][tt];
            s2 += g_csum2[3][t][tt];
        }
        const float inv_n = 1.f / (float)NROW;
        float mean = s * inv_n;
        float var  = s2 * inv_n - mean * mean;
        float a = ga4[t] * rsqrtf(var + 1e-5f);
        aff_a_s[t] = a;
        aff_b_s[t] = be4[t] - mean * a;
    }
    __syncthreads();

    for (int c = t; c < LT * D_; c += 256) {
        int ll = c / D_;
        int ch = c - ll * D_;
        int l  = l0 + ll;
        float v;
        if (ch < F_) {
            v = aff_a_s[ch] * g_act2[(size_t)(b * 100 + l) * F_ + ch] + aff_b_s[ch];
        } else if (ch == F_) {
            v = ((float)l / 10.0f - 2.0f) * 0.5f;
        } else {
            v = ((float)(l % 10) - 2.0f) * 0.5f;
        }
        xf[ll][ch] = v;
    }

    if (t < 128) {
        const float* Wc = W1 + (size_t)(2 * D_) * M_;
        const float* hrow = h + (size_t)b * E_;
        float acc = b1[t];
#pragma unroll 4
        for (int k = 0; k < E_; k++) acc += hrow[k] * Wc[(size_t)k * M_ + t];
        hb_s[t] = acc;
    }
    __syncthreads();

    const int n  = t & 127;
    const int lg = t >> 7;

    float accA[LT / 2], accC[LT / 2];
#pragma unroll
    for (int i = 0; i < LT / 2; i++) { accA[i] = 0.f; accC[i] = 0.f; }

    const float* Wa = W1;
    const float* Wb = W1 + (size_t)D_ * M_;
#pragma unroll 2
    for (int c = 0; c < D_; c++) {
        float wa = Wa[(size_t)c * M_ + n];
        float wb = Wb[(size_t)c * M_ + n];
#pragma unroll
        for (int i = 0; i < LT / 2; i++) {
            float x = xf[2 * i + lg][c];
            accA[i] += x * wa;
            accC[i] += x * wb;
        }
    }
    float hbv = hb_s[n];
#pragma unroll
    for (int i = 0; i < LT / 2; i++) {
        int l = l0 + 2 * i + lg;
        g_A[((size_t)b * L_ + l) * M_ + n] = accA[i];
        g_C[((size_t)b * L_ + l) * M_ + n] = accC[i] + hbv;
    }
}

// =================================================================================
// Tensor-core pairwise relation kernel — fp16 2-term split, 2 blocks/SM.
// =================================================================================
constexpr int SMEM_PW = 128 * 32 * 16;

DEV_INLINE void stageW(uint4* smW, int layer, int tid) {
    const uint4* src = g_wpack2[layer];
#pragma unroll
    for (int it = 0; it < 16; it++)
        smW[it * 256 + tid] = src[it * 256 + tid];
}

__global__ void __launch_bounds__(256, 2) pairwise_mma(
    const float* __restrict__ b2, const float* __restrict__ b3,
    const float* __restrict__ b4)
{
    extern __shared__ char smraw[];
    uint4* smW    = (uint4*)smraw;
    float* s_part = (float*)smraw;

    const int tile = blockIdx.x;
    const int b    = blockIdx.y;
    const int row0 = tile * 128;
    const int tid  = threadIdx.x;
    const int w    = tid >> 5;
    const int lane = tid & 31;
    const int g    = lane >> 2;
    const int t    = lane & 3;

    uint32_t Ah[8][4];
    const int r0 = row0 + 16 * w + g;
    const int r1 = r0 + 8;
    {
        int rc0 = r0 < NPAIR ? r0 : 0;
        int rc1 = r1 < NPAIR ? r1 : 0;
        int i0 = rc0 / 100, j0 = rc0 - (rc0 / 100) * 100;
        int i1 = rc1 / 100, j1 = rc1 - (rc1 / 100) * 100;
        const float2* C0 = (const float2*)(g_C + ((size_t)b * L_ + i0) * M_);
        const float2* A0 = (const float2*)(g_A + ((size_t)b * L_ + j0) * M_);
        const float2* C1 = (const float2*)(g_C + ((size_t)b * L_ + i1) * M_);
        const float2* A1 = (const float2*)(g_A + ((size_t)b * L_ + j1) * M_);
#pragma unroll
        for (int c = 0; c < 8; c++) {
            int idx = 8 * c + t;
            float2 cc, aa;
            cc = C0[idx];     aa = A0[idx];
            Ah[c][0] = pack_h2(lrelu(cc.x + aa.x), lrelu(cc.y + aa.y));
            cc = C1[idx];     aa = A1[idx];
            Ah[c][1] = pack_h2(lrelu(cc.x + aa.x), lrelu(cc.y + aa.y));
            cc = C0[idx + 4]; aa = A0[idx + 4];
            Ah[c][2] = pack_h2(lrelu(cc.x + aa.x), lrelu(cc.y + aa.y));
            cc = C1[idx + 4]; aa = A1[idx + 4];
            Ah[c][3] = pack_h2(lrelu(cc.x + aa.x), lrelu(cc.y + aa.y));
        }
    }

    stageW(smW, 0, tid);
    __syncthreads();

#pragma unroll
    for (int layer = 0; layer < 3; layer++) {
        float acc[16][4];
#pragma unroll
        for (int nt = 0; nt < 16; nt++)
#pragma unroll
            for (int q = 0; q < 4; q++) acc[nt][q] = 0.f;

#pragma unroll
        for (int c = 0; c < 8; c++) {
            const int base_slot = c * 4 + t;
#pragma unroll
            for (int nt = 0; nt < 16; nt++) {
                const int n = nt * 8 + g;
                uint4 f4 = smW[n * 32 + (base_slot ^ ((n & 1) * 4))];
                mma16816_f16(acc[nt], Ah[c], f4.x, f4.y);
                mma16816_f16(acc[nt], Ah[c], f4.z, f4.w);
            }
        }

        if (layer < 2) {
            const float* bias = layer == 0 ? b2 : b3;
#pragma unroll
            for (int nt = 0; nt < 16; nt++) {
                int col = nt * 8 + 2 * t;
                float bb0 = __ldg(bias + col);
                float bb1 = __ldg(bias + col + 1);
                float z0 = lrelu(acc[nt][0] + bb0);
                float z1 = lrelu(acc[nt][1] + bb1);
                float z2 = lrelu(acc[nt][2] + bb0);
                float z3 = lrelu(acc[nt][3] + bb1);
                int c2  = nt >> 1;
                int off = (nt & 1) * 2;
                Ah[c2][off]     = pack_h2(z0, z1);
                Ah[c2][off + 1] = pack_h2(z2, z3);
            }
            __syncthreads();
            stageW(smW, layer + 1, tid);
            __syncthreads();
        } else {
            __syncthreads();
            const bool live0 = r0 < NPAIR;
            const bool live1 = r1 < NPAIR;
#pragma unroll
            for (int nt = 0; nt < 16; nt++) {
                int col = nt * 8 + 2 * t;
                float bb0 = __ldg(b4 + col);
                float bb1 = __ldg(b4 + col + 1);
                float z0 = live0 ? lrelu(acc[nt][0] + bb0) : 0.f;
                float z1 = live0 ? lrelu(acc[nt][1] + bb1) : 0.f;
                float z2 = live1 ? lrelu(acc[nt][2] + bb0) : 0.f;
                float z3 = live1 ? lrelu(acc[nt][3] + bb1) : 0.f;
                float v0 = z0 + z2;
                float v1 = z1 + z3;
#pragma unroll
                for (int o = 4; o < 32; o <<= 1) {
                    v0 += __shfl_xor_sync(0xffffffffu, v0, o);
                    v1 += __shfl_xor_sync(0xffffffffu, v1, o);
                }
                if (g == 0) {
                    s_part[w * 128 + col]     = v0;
                    s_part[w * 128 + col + 1] = v1;
                }
            }
            __syncthreads();
            if (tid < 128) {
                float ss = 0.f;
#pragma unroll
                for (int ww = 0; ww < 8; ww++) ss += s_part[ww * 128 + tid];
                g_part[((size_t)b * NTILE + tile) * M_ + tid] = ss;
            }
        }
    }
}

// =================================================================================
// Final decoder (unchanged)
// =================================================================================
__global__ void __launch_bounds__(128) final_kernel(
    const float* __restrict__ F1, const float* __restrict__ fb1,
    const float* __restrict__ F2, const float* __restrict__ fb2,
    float* __restrict__ out)
{
    const int b = blockIdx.x;
    const int t = threadIdx.x;
    __shared__ float s_s[M_], t_s[M_];

    float acc = 0.f;
    for (int i = 0; i < NTILE; i++)
        acc += g_part[((size_t)b * NTILE + i) * M_ + t];
    s_s[t] = acc;
    __syncthreads();

    float a2 = fb1[t];
#pragma unroll 4
    for (int k = 0; k < M_; k++) a2 += s_s[k] * F1[(size_t)k * M_ + t];
    t_s[t] = lrelu(a2);
    __syncthreads();

    for (int m = t; m < 512; m += 128) {
        float a3 = fb2[m];
#pragma unroll 4
        for (int k = 0; k < M_; k++) a3 += t_s[k] * F2[(size_t)k * 512 + m];
        out[(size_t)b * 512 + m] = lrelu(a3);
    }
}

// =================================================================================
// launcher
// =================================================================================
extern "C" void kernel_launch(void* const* d_in, const int* in_sizes, int n_in,
                              void* d_out, int out_size)
{
    (void)in_sizes; (void)n_in; (void)out_size;

    const float* x   = (const float*)d_in[0];
    const float* h   = (const float*)d_in[1];
    const float* cw1 = (const float*)d_in[2];
    const float* cb1 = (const float*)d_in[3];
    const float* ga1 = (const float*)d_in[4];
    const float* be1 = (const float*)d_in[5];
    const float* cw2 = (const float*)d_in[6];
    const float* cb2 = (const float*)d_in[7];
    const float* ga2 = (const float*)d_in[8];
    const float* be2 = (const float*)d_in[9];
    const float* cw3 = (const float*)d_in[10];
    const float* cb3 = (const float*)d_in[11];
    const float* ga3 = (const float*)d_in[12];
    const float* be3 = (const float*)d_in[13];
    const float* cw4 = (const float*)d_in[14];
    const float* cb4 = (const float*)d_in[15];
    const float* ga4 = (const float*)d_in[16];
    const float* be4 = (const float*)d_in[17];
    const float* W1  = (const float*)d_in[18];
    const float* b1  = (const float*)d_in[19];
    const float* W2  = (const float*)d_in[20];
    const float* b2  = (const float*)d_in[21];
    const float* W3  = (const float*)d_in[22];
    const float* b3  = (const float*)d_in[23];
    const float* W4  = (const float*)d_in[24];
    const float* b4  = (const float*)d_in[25];
    const float* F1  = (const float*)d_in[26];
    const float* fb1 = (const float*)d_in[27];
    const float* F2  = (const float*)d_in[28];
    const float* fb2 = (const float*)d_in[29];
    float* out = (float*)d_out;

    cudaFuncSetAttribute(conv_mma<E_, true >,
                         cudaFuncAttributeMaxDynamicSharedMemorySize, CSMEM);
    cudaFuncSetAttribute(conv_mma<F_, false>,
                         cudaFuncAttributeMaxDynamicSharedMemorySize, CSMEM);
    cudaFuncSetAttribute(pairwise_mma,
                         cudaFuncAttributeMaxDynamicSharedMemorySize, SMEM_PW);

    dim3 cgrid(RTILE, 4);

    // 0: one-time conv weight pack
    pack_conv<<<(CWP_TOTAL + 255) / 256, 256>>>(cw1, cw2, cw3, cw4);

    // 1..4: tensor-core conv stack with fused BN stats
    conv_mma<E_, true ><<<cgrid, 256, CSMEM>>>(x, 0, 0, nullptr, nullptr, CB0, cb1, 0, 0);
    conv_mma<F_, false><<<cgrid, 256, CSMEM>>>(nullptr, 0, 0, ga1, be1, CB1, cb2, 1, 1);
    conv_mma<F_, false><<<cgrid, 256, CSMEM>>>(nullptr, 1, 1, ga2, be2, CB2, cb3, 0, 2);
    conv_mma<F_, false><<<cgrid, 256, CSMEM>>>(nullptr, 0, 2, ga3, be3, CB3, cb4, 1, 3);

    // 5: projections
    ac_kernel<<<dim3(B_, 6), 256>>>(W1, b1, h, ga4, be4, W2, W3, W4);

    // 6: tensor-core pairwise chain
    pairwise_mma<<<dim3(NTILE, B_), 256, SMEM_PW>>>(b2, b3, b4);

    // 7: decoder
    final_kernel<<<B_, 128>>>(F1, fb1, F2, fb2, out);
}

// round 14
// speedup vs baseline: 2.0913x; 1.0094x over previous
#include <cuda_runtime.h>
#include <cuda_fp16.h>
#include <cstdint>

#define DEV_INLINE __device__ __forceinline__

constexpr int L_   = 100;
constexpr int B_   = 32;
constexpr int E_   = 512;
constexpr int F_   = 256;
constexpr int M_   = 128;
constexpr int D_   = 258;
constexpr int NPAIR = L_ * L_;                 // 10000
constexpr int NTILE = (NPAIR + 127) / 128;     // 79
constexpr int NJOB  = NTILE * B_;              // 2528
constexpr int NROW  = B_ * L_;                 // 3200 = 25 * 128
constexpr int RTILE = 25;

// packed conv-weight fragment array bases (uint4 units)
constexpr int CB0 = 0;
constexpr int CB1 = 98304;
constexpr int CB2 = 147456;
constexpr int CB3 = 196608;
constexpr int CWP_TOTAL = 245760;

// ---------------- scratch (device globals; no allocation allowed) ----------------
__device__ float g_act1[NROW * F_];
__device__ float g_act2[NROW * F_];
__device__ float g_csum [4][F_][32];
__device__ float g_csum2[4][F_][32];
__device__ float g_A[B_ * L_ * M_];
__device__ float g_C[B_ * L_ * M_];
__device__ float g_part[B_ * NTILE * M_];
__device__ __align__(16) uint4 g_wpack2[3][128 * 32];   // pairwise weights
__device__ __align__(16) uint4 g_cwp[CWP_TOTAL];        // conv weights (fragments)

DEV_INLINE float lrelu(float z) { return fmaxf(z, 0.f) + 0.1f * fminf(z, 0.f); }

DEV_INLINE uint32_t pack_h2(float x0, float x1) {
    __half2 h = __floats2half2_rn(x0, x1);
    return *reinterpret_cast<uint32_t*>(&h);
}

DEV_INLINE void split2h(float x0, float x1, uint32_t& hi, uint32_t& lo) {
    __half h0 = __float2half_rn(x0);
    __half h1 = __float2half_rn(x1);
    float r0 = x0 - __half2float(h0);
    float r1 = x1 - __half2float(h1);
    __half2 hh = __halves2half2(h0, h1);
    hi = *reinterpret_cast<uint32_t*>(&hh);
    lo = pack_h2(r0, r1);
}

DEV_INLINE void mma16816_f16(float c[4], const uint32_t a[4], uint32_t b0, uint32_t b1) {
    asm volatile(
        "mma.sync.aligned.m16n8k16.row.col.f32.f16.f16.f32 "
        "{%0,%1,%2,%3}, {%4,%5,%6,%7}, {%8,%9}, {%0,%1,%2,%3};"
        : "+f"(c[0]), "+f"(c[1]), "+f"(c[2]), "+f"(c[3])
        : "r"(a[0]), "r"(a[1]), "r"(a[2]), "r"(a[3]), "r"(b0), "r"(b1));
}

// =================================================================================
// One-time conv weight pack (fp16 hi/lo fragment uint4s; layout matches conv MMA).
// =================================================================================
__global__ void __launch_bounds__(256) pack_conv(
    const float* __restrict__ cw1, const float* __restrict__ cw2,
    const float* __restrict__ cw3, const float* __restrict__ cw4)
{
    int idx = blockIdx.x * 256 + threadIdx.x;
    if (idx >= CWP_TOTAL) return;
    const float* cw; int EIN, NKC, rem;
    if (idx < CB1)      { rem = idx;       cw = cw1; EIN = 512; NKC = 4; }
    else if (idx < CB2) { rem = idx - CB1; cw = cw2; EIN = 256; NKC = 2; }
    else if (idx < CB3) { rem = idx - CB2; cw = cw3; EIN = 256; NKC = 2; }
    else                { rem = idx - CB3; cw = cw4; EIN = 256; NKC = 2; }
    int per_by = 3 * NKC * 2048;
    int by = rem / per_by;
    int r2 = rem - by * per_by;
    int s  = r2 / (NKC * 2048);
    int r3 = r2 - s * (NKC * 2048);
    int kc = r3 >> 11;
    int id = r3 & 2047;
    int n  = id >> 5;
    int j  = id & 31;
    int jj = j ^ ((n & 1) * 4);
    int e0 = 128 * kc + 16 * (jj >> 2) + 2 * (jj & 3);
    const float* wp = cw + ((size_t)(by * 64 + n) * EIN + e0) * 3 + s;
    float v0 = wp[0], v1 = wp[3], v2 = wp[24], v3 = wp[27];
    uint32_t h01, l01, h23, l23;
    split2h(v0, v1, h01, l01);
    split2h(v2, v3, h23, l23);
    g_cwp[idx] = make_uint4(h01, h23, l01, l23);
}

// =================================================================================
// Tensor-core Conv1d (K=3, pad 1) + bias + leakyReLU + fused BN stats (R13, proven)
// =================================================================================
constexpr int CSMEM = 32768 + 4096 + 4096;

template <int EIN, bool FIRST>
__global__ void __launch_bounds__(256, 2) conv_mma(
    const float* __restrict__ x_ext,
    int src, int prev_layer,
    const float* __restrict__ ga_prev, const float* __restrict__ be_prev,
    int wbase,
    const float* __restrict__ cb,
    int dst, int stat_layer)
{
    constexpr int NKC = EIN / 128;
    extern __shared__ char smraw[];
    uint4*  smW     = (uint4*)smraw;
    float*  aff_a_s = (float*)(smraw + 32768);
    float*  aff_b_s = aff_a_s + EIN;
    float*  s_sum   = (float*)(smraw + 32768 + 4096);
    float*  s_sq    = s_sum + 512;

    const int tile = blockIdx.x;
    const int by   = blockIdx.y;
    const int f0   = by * 64;
    const int row0 = tile * 128;
    const int tid  = threadIdx.x;
    const int w    = tid >> 5;
    const int lane = tid & 31;
    const int g    = lane >> 2;
    const int t    = lane & 3;

    if (!FIRST) {
        for (int ch = tid; ch < EIN; ch += 256) {
            float s = 0.f, s2 = 0.f;
#pragma unroll
            for (int tt = 0; tt < RTILE; tt++) {
                s  += g_csum [prev_layer][ch][tt];
                s2 += g_csum2[prev_layer][ch][tt];
            }
            const float inv_n = 1.f / (float)NROW;
            float mean = s * inv_n;
            float var  = s2 * inv_n - mean * mean;
            float a = ga_prev[ch] * rsqrtf(var + 1e-5f);
            aff_a_s[ch] = a;
            aff_b_s[ch] = be_prev[ch] - mean * a;
        }
        __syncthreads();
    }

    const int r0 = row0 + 16 * w + g;
    const int r1 = r0 + 8;
    const int b0r = r0 / 100, l0r = r0 - b0r * 100;
    const int b1r = r1 / 100, l1r = r1 - b1r * 100;

    const float* act_in = src ? g_act2 : g_act1;

    float acc[8][4];
#pragma unroll
    for (int nt = 0; nt < 8; nt++)
#pragma unroll
        for (int q = 0; q < 4; q++) acc[nt][q] = 0.f;

#pragma unroll 1
    for (int s = 0; s < 3; s++) {
        const bool m0 = (unsigned)(l0r + s - 1) < 100u;
        const bool m1 = (unsigned)(l1r + s - 1) < 100u;
        const float* p0;
        const float* p1;
        if (FIRST) {
            p0 = x_ext + ((size_t)(m0 ? (l0r + s - 1) : 0) * B_ + b0r) * E_;
            p1 = x_ext + ((size_t)(m1 ? (l1r + s - 1) : 0) * B_ + b1r) * E_;
        } else {
            p0 = act_in + (size_t)(m0 ? (r0 + s - 1) : r0) * EIN;
            p1 = act_in + (size_t)(m1 ? (r1 + s - 1) : r1) * EIN;
        }

#pragma unroll 1
        for (int kc = 0; kc < NKC; kc++) {
            __syncthreads();
            {
                const uint4* srcW = g_cwp + wbase + (((by * 3 + s) * NKC + kc) << 11);
#pragma unroll
                for (int it = 0; it < 8; it++)
                    smW[it * 256 + tid] = srcW[it * 256 + tid];
            }
            __syncthreads();

            uint32_t Ah[8][4];
#pragma unroll
            for (int c = 0; c < 8; c++) {
                int e0 = 128 * kc + 16 * c + 2 * t;
                float2 x00 = m0 ? *(const float2*)(p0 + e0)     : make_float2(0.f, 0.f);
                float2 x01 = m1 ? *(const float2*)(p1 + e0)     : make_float2(0.f, 0.f);
                float2 x10 = m0 ? *(const float2*)(p0 + e0 + 8) : make_float2(0.f, 0.f);
                float2 x11 = m1 ? *(const float2*)(p1 + e0 + 8) : make_float2(0.f, 0.f);
                if (!FIRST) {
                    float a0 = aff_a_s[e0],     bA0 = aff_b_s[e0];
                    float a1 = aff_a_s[e0 + 1], bA1 = aff_b_s[e0 + 1];
                    float a8 = aff_a_s[e0 + 8], bA8 = aff_b_s[e0 + 8];
                    float a9 = aff_a_s[e0 + 9], bA9 = aff_b_s[e0 + 9];
                    if (m0) { x00.x = fmaf(a0, x00.x, bA0); x00.y = fmaf(a1, x00.y, bA1);
                              x10.x = fmaf(a8, x10.x, bA8); x10.y = fmaf(a9, x10.y, bA9); }
                    if (m1) { x01.x = fmaf(a0, x01.x, bA0); x01.y = fmaf(a1, x01.y, bA1);
                              x11.x = fmaf(a8, x11.x, bA8); x11.y = fmaf(a9, x11.y, bA9); }
                }
                Ah[c][0] = pack_h2(x00.x, x00.y);
                Ah[c][1] = pack_h2(x01.x, x01.y);
                Ah[c][2] = pack_h2(x10.x, x10.y);
                Ah[c][3] = pack_h2(x11.x, x11.y);
            }

#pragma unroll
            for (int c = 0; c < 8; c++) {
                const int bslot = c * 4 + t;
#pragma unroll
                for (int nt = 0; nt < 8; nt++) {
                    const int n = nt * 8 + g;
                    uint4 f4 = smW[n * 32 + (bslot ^ ((n & 1) * 4))];
                    mma16816_f16(acc[nt], Ah[c], f4.x, f4.y);
                    mma16816_f16(acc[nt], Ah[c], f4.z, f4.w);
                }
            }
        }
    }

    float* out = dst ? g_act2 : g_act1;
#pragma unroll
    for (int nt = 0; nt < 8; nt++) {
        int col = nt * 8 + 2 * t;
        float bb0 = __ldg(cb + f0 + col);
        float bb1 = __ldg(cb + f0 + col + 1);
        float z0 = lrelu(acc[nt][0] + bb0);
        float z1 = lrelu(acc[nt][1] + bb1);
        float z2 = lrelu(acc[nt][2] + bb0);
        float z3 = lrelu(acc[nt][3] + bb1);
        *(float2*)(out + (size_t)r0 * F_ + f0 + col) = make_float2(z0, z1);
        *(float2*)(out + (size_t)r1 * F_ + f0 + col) = make_float2(z2, z3);
        float s0 = z0 + z2, s1 = z1 + z3;
        float q0 = z0 * z0 + z2 * z2, q1 = z1 * z1 + z3 * z3;
#pragma unroll
        for (int o = 4; o < 32; o <<= 1) {
            s0 += __shfl_xor_sync(0xffffffffu, s0, o);
            s1 += __shfl_xor_sync(0xffffffffu, s1, o);
            q0 += __shfl_xor_sync(0xffffffffu, q0, o);
            q1 += __shfl_xor_sync(0xffffffffu, q1, o);
        }
        if (g == 0) {
            s_sum[w * 64 + col]     = s0;
            s_sum[w * 64 + col + 1] = s1;
            s_sq [w * 64 + col]     = q0;
            s_sq [w * 64 + col + 1] = q1;
        }
    }
    __syncthreads();
    if (tid < 64) {
        float s = 0.f, q = 0.f;
#pragma unroll
        for (int ww = 0; ww < 8; ww++) {
            s += s_sum[ww * 64 + tid];
            q += s_sq [ww * 64 + tid];
        }
        g_csum [stat_layer][f0 + tid][tile] = s;
        g_csum2[stat_layer][f0 + tid][tile] = q;
    }
}

// =================================================================================
// A / C projections with fused hb, layer-4 affine, and pairwise weight packing.
// =================================================================================
constexpr int LT = 20;

__global__ void __launch_bounds__(256) ac_kernel(
    const float* __restrict__ W1, const float* __restrict__ b1,
    const float* __restrict__ h,
    const float* __restrict__ ga4, const float* __restrict__ be4,
    const float* __restrict__ W2, const float* __restrict__ W3,
    const float* __restrict__ W4)
{
    if (blockIdx.y == 5) {
        for (int idx = blockIdx.x * 256 + threadIdx.x; idx < 3 * 128 * 32;
             idx += 32 * 256) {
            int layer = idx >> 12;
            int rem   = idx & 4095;
            int n = rem >> 5;
            int s = rem & 31;
            int c = s >> 2;
            int t = s & 3;
            const float* W = layer == 0 ? W2 : (layer == 1 ? W3 : W4);
            uint32_t hw[2], lw[2];
#pragma unroll
            for (int j = 0; j < 2; j++) {
                int kw = 8 * c + 4 * j + t;
                float w0 = W[(size_t)(2 * kw) * 128 + n];
                float w1 = W[(size_t)(2 * kw + 1) * 128 + n];
                split2h(w0, w1, hw[j], lw[j]);
            }
            int slot = (c * 4 + t) ^ ((n & 1) * 4);
            g_wpack2[layer][n * 32 + slot] = make_uint4(hw[0], hw[1], lw[0], lw[1]);
        }
        return;
    }

    __shared__ float xf[LT][D_];
    __shared__ float aff_a_s[F_], aff_b_s[F_];
    __shared__ float hb_s[M_];

    const int b  = blockIdx.x;
    const int l0 = blockIdx.y * LT;
    const int t  = threadIdx.x;

    if (t < F_) {
        float s = 0.f, s2 = 0.f;
#pragma unroll
        for (int tt = 0; tt < RTILE; tt++) {
            s  += g_csum [3][t][tt];
            s2 += g_csum2[3][t][tt];
        }
        const float inv_n = 1.f / (float)NROW;
        float mean = s * inv_n;
        float var  = s2 * inv_n - mean * mean;
        float a = ga4[t] * rsqrtf(var + 1e-5f);
        aff_a_s[t] = a;
        aff_b_s[t] = be4[t] - mean * a;
    }
    __syncthreads();

    for (int c = t; c < LT * D_; c += 256) {
        int ll = c / D_;
        int ch = c - ll * D_;
        int l  = l0 + ll;
        float v;
        if (ch < F_) {
            v = aff_a_s[ch] * g_act2[(size_t)(b * 100 + l) * F_ + ch] + aff_b_s[ch];
        } else if (ch == F_) {
            v = ((float)l / 10.0f - 2.0f) * 0.5f;
        } else {
            v = ((float)(l % 10) - 2.0f) * 0.5f;
        }
        xf[ll][ch] = v;
    }

    if (t < 128) {
        const float* Wc = W1 + (size_t)(2 * D_) * M_;
        const float* hrow = h + (size_t)b * E_;
        float acc = b1[t];
#pragma unroll 4
        for (int k = 0; k < E_; k++) acc += hrow[k] * Wc[(size_t)k * M_ + t];
        hb_s[t] = acc;
    }
    __syncthreads();

    const int n  = t & 127;
    const int lg = t >> 7;

    float accA[LT / 2], accC[LT / 2];
#pragma unroll
    for (int i = 0; i < LT / 2; i++) { accA[i] = 0.f; accC[i] = 0.f; }

    const float* Wa = W1;
    const float* Wb = W1 + (size_t)D_ * M_;
#pragma unroll 2
    for (int c = 0; c < D_; c++) {
        float wa = Wa[(size_t)c * M_ + n];
        float wb = Wb[(size_t)c * M_ + n];
#pragma unroll
        for (int i = 0; i < LT / 2; i++) {
            float x = xf[2 * i + lg][c];
            accA[i] += x * wa;
            accC[i] += x * wb;
        }
    }
    float hbv = hb_s[n];
#pragma unroll
    for (int i = 0; i < LT / 2; i++) {
        int l = l0 + 2 * i + lg;
        g_A[((size_t)b * L_ + l) * M_ + n] = accA[i];
        g_C[((size_t)b * L_ + l) * M_ + n] = accC[i] + hbv;
    }
}

// =================================================================================
// PERSISTENT tensor-core pairwise relation kernel.
// 148 blocks; each stages ALL THREE weight layers (3 x 64KB) once, then loops
// over (tile, b) jobs. The 3-layer chain per job is sync-free (activations stay
// in registers); only the per-job column reduction uses smem + 2 syncs.
// =================================================================================
constexpr int SMEM_PW = 3 * 65536 + 4096;   // 200,704 B
constexpr int PW_GRID = 148;

__global__ void __launch_bounds__(256) pairwise_mma(
    const float* __restrict__ b2, const float* __restrict__ b3,
    const float* __restrict__ b4)
{
    extern __shared__ char smraw[];
    uint4* smW    = (uint4*)smraw;                    // [3][4096]
    float* s_part = (float*)(smraw + 3 * 65536);      // [8][128]

    const int tid  = threadIdx.x;
    const int w    = tid >> 5;
    const int lane = tid & 31;
    const int g    = lane >> 2;
    const int t    = lane & 3;

    // ---- stage all three layers' weights once ----
    {
        const uint4* src = g_wpack2[0];   // 3 contiguous layers = 12288 uint4
#pragma unroll
        for (int it = 0; it < 48; it++)
            smW[it * 256 + tid] = src[it * 256 + tid];
    }
    __syncthreads();

    for (int job = blockIdx.x; job < NJOB; job += PW_GRID) {
        const int b    = job & 31;
        const int tile = job >> 5;
        const int row0 = tile * 128;
        const int r0 = row0 + 16 * w + g;
        const int r1 = r0 + 8;

        // ---- build layer-1 A fragments: g1 = lrelu(C_i + A_j), fp16 ----
        uint32_t Ah[8][4];
        {
            int rc0 = r0 < NPAIR ? r0 : 0;
            int rc1 = r1 < NPAIR ? r1 : 0;
            int i0 = rc0 / 100, j0 = rc0 - (rc0 / 100) * 100;
            int i1 = rc1 / 100, j1 = rc1 - (rc1 / 100) * 100;
            const float2* C0 = (const float2*)(g_C + ((size_t)b * L_ + i0) * M_);
            const float2* A0 = (const float2*)(g_A + ((size_t)b * L_ + j0) * M_);
            const float2* C1 = (const float2*)(g_C + ((size_t)b * L_ + i1) * M_);
            const float2* A1 = (const float2*)(g_A + ((size_t)b * L_ + j1) * M_);
#pragma unroll
            for (int c = 0; c < 8; c++) {
                int idx = 8 * c + t;
                float2 cc, aa;
                cc = C0[idx];     aa = A0[idx];
                Ah[c][0] = pack_h2(lrelu(cc.x + aa.x), lrelu(cc.y + aa.y));
                cc = C1[idx];     aa = A1[idx];
                Ah[c][1] = pack_h2(lrelu(cc.x + aa.x), lrelu(cc.y + aa.y));
                cc = C0[idx + 4]; aa = A0[idx + 4];
                Ah[c][2] = pack_h2(lrelu(cc.x + aa.x), lrelu(cc.y + aa.y));
                cc = C1[idx + 4]; aa = A1[idx + 4];
                Ah[c][3] = pack_h2(lrelu(cc.x + aa.x), lrelu(cc.y + aa.y));
            }
        }

#pragma unroll
        for (int layer = 0; layer < 3; layer++) {
            const uint4* smWL = smW + (layer << 12);
            float acc[16][4];
#pragma unroll
            for (int nt = 0; nt < 16; nt++)
#pragma unroll
                for (int q = 0; q < 4; q++) acc[nt][q] = 0.f;

#pragma unroll
            for (int c = 0; c < 8; c++) {
                const int base_slot = c * 4 + t;
#pragma unroll
                for (int nt = 0; nt < 16; nt++) {
                    const int n = nt * 8 + g;
                    uint4 f4 = smWL[n * 32 + (base_slot ^ ((n & 1) * 4))];
                    mma16816_f16(acc[nt], Ah[c], f4.x, f4.y);
                    mma16816_f16(acc[nt], Ah[c], f4.z, f4.w);
                }
            }

            if (layer < 2) {
                const float* bias = layer == 0 ? b2 : b3;
#pragma unroll
                for (int nt = 0; nt < 16; nt++) {
                    int col = nt * 8 + 2 * t;
                    float bb0 = __ldg(bias + col);
                    float bb1 = __ldg(bias + col + 1);
                    float z0 = lrelu(acc[nt][0] + bb0);
                    float z1 = lrelu(acc[nt][1] + bb1);
                    float z2 = lrelu(acc[nt][2] + bb0);
                    float z3 = lrelu(acc[nt][3] + bb1);
                    int c2  = nt >> 1;
                    int off = (nt & 1) * 2;
                    Ah[c2][off]     = pack_h2(z0, z1);
                    Ah[c2][off + 1] = pack_h2(z2, z3);
                }
                // no sync: weights are read-only resident, activations in regs
            } else {
                const bool live0 = r0 < NPAIR;
                const bool live1 = r1 < NPAIR;
#pragma unroll
                for (int nt = 0; nt < 16; nt++) {
                    int col = nt * 8 + 2 * t;
                    float bb0 = __ldg(b4 + col);
                    float bb1 = __ldg(b4 + col + 1);
                    float z0 = live0 ? lrelu(acc[nt][0] + bb0) : 0.f;
                    float z1 = live0 ? lrelu(acc[nt][1] + bb1) : 0.f;
                    float z2 = live1 ? lrelu(acc[nt][2] + bb0) : 0.f;
                    float z3 = live1 ? lrelu(acc[nt][3] + bb1) : 0.f;
                    float v0 = z0 + z2;
                    float v1 = z1 + z3;
#pragma unroll
                    for (int o = 4; o < 32; o <<= 1) {
                        v0 += __shfl_xor_sync(0xffffffffu, v0, o);
                        v1 += __shfl_xor_sync(0xffffffffu, v1, o);
                    }
                    if (g == 0) {
                        s_part[w * 128 + col]     = v0;
                        s_part[w * 128 + col + 1] = v1;
                    }
                }
                __syncthreads();
                if (tid < 128) {
                    float ss = 0.f;
#pragma unroll
                    for (int ww = 0; ww < 8; ww++) ss += s_part[ww * 128 + tid];
                    g_part[((size_t)b * NTILE + tile) * M_ + tid] = ss;
                }
                __syncthreads();   // s_part reusable for next job
            }
        }
    }
}

// =================================================================================
// Final decoder (unchanged)
// =================================================================================
__global__ void __launch_bounds__(128) final_kernel(
    const float* __restrict__ F1, const float* __restrict__ fb1,
    const float* __restrict__ F2, const float* __restrict__ fb2,
    float* __restrict__ out)
{
    const int b = blockIdx.x;
    const int t = threadIdx.x;
    __shared__ float s_s[M_], t_s[M_];

    float acc = 0.f;
    for (int i = 0; i < NTILE; i++)
        acc += g_part[((size_t)b * NTILE + i) * M_ + t];
    s_s[t] = acc;
    __syncthreads();

    float a2 = fb1[t];
#pragma unroll 4
    for (int k = 0; k < M_; k++) a2 += s_s[k] * F1[(size_t)k * M_ + t];
    t_s[t] = lrelu(a2);
    __syncthreads();

    for (int m = t; m < 512; m += 128) {
        float a3 = fb2[m];
#pragma unroll 4
        for (int k = 0; k < M_; k++) a3 += t_s[k] * F2[(size_t)k * 512 + m];
        out[(size_t)b * 512 + m] = lrelu(a3);
    }
}

// =================================================================================
// launcher
// =================================================================================
extern "C" void kernel_launch(void* const* d_in, const int* in_sizes, int n_in,
                              void* d_out, int out_size)
{
    (void)in_sizes; (void)n_in; (void)out_size;

    const float* x   = (const float*)d_in[0];
    const float* h   = (const float*)d_in[1];
    const float* cw1 = (const float*)d_in[2];
    const float* cb1 = (const float*)d_in[3];
    const float* ga1 = (const float*)d_in[4];
    const float* be1 = (const float*)d_in[5];
    const float* cw2 = (const float*)d_in[6];
    const float* cb2 = (const float*)d_in[7];
    const float* ga2 = (const float*)d_in[8];
    const float* be2 = (const float*)d_in[9];
    const float* cw3 = (const float*)d_in[10];
    const float* cb3 = (const float*)d_in[11];
    const float* ga3 = (const float*)d_in[12];
    const float* be3 = (const float*)d_in[13];
    const float* cw4 = (const float*)d_in[14];
    const float* cb4 = (const float*)d_in[15];
    const float* ga4 = (const float*)d_in[16];
    const float* be4 = (const float*)d_in[17];
    const float* W1  = (const float*)d_in[18];
    const float* b1  = (const float*)d_in[19];
    const float* W2  = (const float*)d_in[20];
    const float* b2  = (const float*)d_in[21];
    const float* W3  = (const float*)d_in[22];
    const float* b3  = (const float*)d_in[23];
    const float* W4  = (const float*)d_in[24];
    const float* b4  = (const float*)d_in[25];
    const float* F1  = (const float*)d_in[26];
    const float* fb1 = (const float*)d_in[27];
    const float* F2  = (const float*)d_in[28];
    const float* fb2 = (const float*)d_in[29];
    float* out = (float*)d_out;

    cudaFuncSetAttribute(conv_mma<E_, true >,
                         cudaFuncAttributeMaxDynamicSharedMemorySize, CSMEM);
    cudaFuncSetAttribute(conv_mma<F_, false>,
                         cudaFuncAttributeMaxDynamicSharedMemorySize, CSMEM);
    cudaFuncSetAttribute(pairwise_mma,
                         cudaFuncAttributeMaxDynamicSharedMemorySize, SMEM_PW);

    dim3 cgrid(RTILE, 4);

    // 0: one-time conv weight pack
    pack_conv<<<(CWP_TOTAL + 255) / 256, 256>>>(cw1, cw2, cw3, cw4);

    // 1..4: tensor-core conv stack with fused BN stats
    conv_mma<E_, true ><<<cgrid, 256, CSMEM>>>(x, 0, 0, nullptr, nullptr, CB0, cb1, 0, 0);
    conv_mma<F_, false><<<cgrid, 256, CSMEM>>>(nullptr, 0, 0, ga1, be1, CB1, cb2, 1, 1);
    conv_mma<F_, false><<<cgrid, 256, CSMEM>>>(nullptr, 1, 1, ga2, be2, CB2, cb3, 0, 2);
    conv_mma<F_, false><<<cgrid, 256, CSMEM>>>(nullptr, 0, 2, ga3, be3, CB3, cb4, 1, 3);

    // 5: projections (fused hb + layer-4 affine + pairwise weight packing)
    ac_kernel<<<dim3(B_, 6), 256>>>(W1, b1, h, ga4, be4, W2, W3, W4);

    // 6: persistent tensor-core pairwise chain
    pairwise_mma<<<PW_GRID, 256, SMEM_PW>>>(b2, b3, b4);

    // 7: decoder
    final_kernel<<<B_, 128>>>(F1, fb1, F2, fb2, out);
}